// round 1
// baseline (speedup 1.0000x reference)
#include <cuda_runtime.h>
#include <math.h>

// ---------------- problem constants ----------------
#define BB   8
#define SS   512
#define DD   768
#define HH   12
#define DH   64
#define EE   14
#define KK   4
#define HID  1536
#define SHH  3072
#define NTOK (BB*SS)          // 4096
#define BHN  (BB*HH)          // 96

// ---------------- scratch (device globals; no allocation) ----------------
__device__ float g_h1  [(size_t)NTOK*DD];
__device__ float g_q   [(size_t)BHN*SS*DH];
__device__ float g_k   [(size_t)BHN*SS*DH];
__device__ float g_v   [(size_t)BHN*SS*DH];
__device__ float g_att [(size_t)BHN*SS*SS];          // 100 MB
__device__ float g_ao  [(size_t)NTOK*DD];
__device__ float g_x2  [(size_t)NTOK*DD];
__device__ float g_h2  [(size_t)NTOK*DD];
__device__ float g_seq [(size_t)BB*DD];
__device__ float g_wgt [(size_t)BB*EE];
__device__ float g_ehid[(size_t)EE*BB*SS*HID];       // 352 MB
__device__ float g_y   [(size_t)NTOK*DD];
__device__ float g_shid[(size_t)NTOK*SHH];           // 50 MB

// ---------------- helpers ----------------
__device__ __forceinline__ float geluf(float x) {
    return 0.5f * x * (1.0f + erff(x * 0.70710678118654752f));
}

__device__ __forceinline__ float blockReduceSum(float v, float* sh) {
    int tid = threadIdx.x;
    sh[tid] = v; __syncthreads();
    for (int s = 128; s > 0; s >>= 1) {
        if (tid < s) sh[tid] += sh[tid + s];
        __syncthreads();
    }
    float r = sh[0]; __syncthreads();
    return r;
}

// 64x64 output tile, BK=16, 256 threads, each thread 4x4.
// A row-major (pre-offset to tile row 0, k=0), B row-major (pre-offset to k=0, tile col 0).
__device__ __forceinline__ void gemm64(const float* __restrict__ A, int lda,
                                       const float* __restrict__ B, int ldb,
                                       int K, float acc[4][4],
                                       float* sA, float* sB)
{
    const int tid = threadIdx.x;
    const int tx = tid & 15, ty = tid >> 4;
    for (int t0 = 0; t0 < K; t0 += 16) {
#pragma unroll
        for (int e = tid; e < 1024; e += 256) {
            int m = e >> 4, k = e & 15;
            sA[k * 64 + m] = A[(size_t)m * lda + (t0 + k)];
        }
#pragma unroll
        for (int e = tid; e < 1024; e += 256) {
            int k = e >> 6, n = e & 63;
            sB[k * 64 + n] = B[(size_t)(t0 + k) * ldb + n];
        }
        __syncthreads();
#pragma unroll
        for (int kk = 0; kk < 16; kk++) {
            float4 a4 = *(const float4*)(sA + kk * 64 + ty * 4);
            float4 b4 = *(const float4*)(sB + kk * 64 + tx * 4);
            float av[4] = {a4.x, a4.y, a4.z, a4.w};
            float bv[4] = {b4.x, b4.y, b4.z, b4.w};
#pragma unroll
            for (int i = 0; i < 4; i++)
#pragma unroll
                for (int j = 0; j < 4; j++)
                    acc[i][j] = fmaf(av[i], bv[j], acc[i][j]);
        }
        __syncthreads();
    }
}

// ---------------- kernels ----------------

// LayerNorm over last dim (768 = 3*256), one block per token
__global__ void ln_kernel(const float* __restrict__ in, const float* __restrict__ g,
                          const float* __restrict__ b, float* __restrict__ out)
{
    __shared__ float red[256];
    size_t row = blockIdx.x;
    const float* xr = in + row * DD;
    int tid = threadIdx.x;
    float x0 = xr[tid], x1 = xr[tid + 256], x2 = xr[tid + 512];
    float total = blockReduceSum(x0 + x1 + x2, red);
    float mean = total * (1.0f / DD);
    float d0 = x0 - mean, d1 = x1 - mean, d2 = x2 - mean;
    float var = blockReduceSum(d0 * d0 + d1 * d1 + d2 * d2, red) * (1.0f / DD);
    float rstd = rsqrtf(var + 1e-5f);
    out[row * DD + tid]       = d0 * rstd * g[tid]       + b[tid];
    out[row * DD + tid + 256] = d1 * rstd * g[tid + 256] + b[tid + 256];
    out[row * DD + tid + 512] = d2 * rstd * g[tid + 512] + b[tid + 512];
}

// QKV GEMM: [4096,768] @ [768,2304], scatter to q/k/v in [B,H,S,dh]
__global__ void qkv_gemm_kernel(const float* __restrict__ W)
{
    __shared__ float sA[1024], sB[1024];
    int row0 = blockIdx.y * 64, col0 = blockIdx.x * 64;
    float acc[4][4] = {};
    gemm64(g_h1 + (size_t)row0 * DD, DD, W + col0, 3 * DD, DD, acc, sA, sB);
    int tid = threadIdx.x, tx = tid & 15, ty = tid >> 4;
#pragma unroll
    for (int i = 0; i < 4; i++) {
        int m = row0 + ty * 4 + i;
        int b = m >> 9, s = m & 511;
#pragma unroll
        for (int j = 0; j < 4; j++) {
            int n = col0 + tx * 4 + j;
            int which = n / DD;
            int rem = n - which * DD;
            int h = rem >> 6, d = rem & 63;
            float* dst = (which == 0) ? g_q : ((which == 1) ? g_k : g_v);
            dst[(((size_t)b * HH + h) * SS + s) * DH + d] = acc[i][j];
        }
    }
}

// scores[bh][q][k] = scale * dot(q_row, k_row)
__global__ void attn_scores_kernel()
{
    __shared__ float sQ[64 * 68], sK[64 * 68];
    int bh = blockIdx.z;
    int q0 = blockIdx.y * 64, k0 = blockIdx.x * 64;
    const float* Q  = g_q + ((size_t)bh * SS + q0) * DH;
    const float* Kp = g_k + ((size_t)bh * SS + k0) * DH;
    int tid = threadIdx.x;
    for (int e = tid; e < 4096; e += 256) {
        int r = e >> 6, c = e & 63;      // consecutive tid -> consecutive c (coalesced)
        sQ[c * 68 + r] = Q[r * 64 + c];
        sK[c * 68 + r] = Kp[r * 64 + c];
    }
    __syncthreads();
    int tx = tid & 15, ty = tid >> 4;
    float acc[4][4] = {};
#pragma unroll 8
    for (int d = 0; d < 64; d++) {
        float4 a4 = *(const float4*)(sQ + d * 68 + ty * 4);
        float4 b4 = *(const float4*)(sK + d * 68 + tx * 4);
        float av[4] = {a4.x, a4.y, a4.z, a4.w};
        float bv[4] = {b4.x, b4.y, b4.z, b4.w};
#pragma unroll
        for (int i = 0; i < 4; i++)
#pragma unroll
            for (int j = 0; j < 4; j++)
                acc[i][j] = fmaf(av[i], bv[j], acc[i][j]);
    }
    float* out = g_att + ((size_t)bh * SS + q0) * SS + k0;
#pragma unroll
    for (int i = 0; i < 4; i++)
#pragma unroll
        for (int j = 0; j < 4; j++)
            out[(size_t)(ty * 4 + i) * SS + tx * 4 + j] = acc[i][j] * 0.125f;
}

// row softmax, 512 cols, one block per row
__global__ void softmax_kernel()
{
    __shared__ float sh[256];
    size_t row = blockIdx.x;
    float* r = g_att + row * SS;
    int tid = threadIdx.x;
    float a = r[tid], b = r[tid + 256];
    sh[tid] = fmaxf(a, b); __syncthreads();
    for (int s = 128; s > 0; s >>= 1) {
        if (tid < s) sh[tid] = fmaxf(sh[tid], sh[tid + s]);
        __syncthreads();
    }
    float mx = sh[0]; __syncthreads();
    a = expf(a - mx); b = expf(b - mx);
    float total = blockReduceSum(a + b, sh);
    float inv = 1.0f / total;
    r[tid] = a * inv;
    r[tid + 256] = b * inv;
}

// out[bh][s][:] = att[bh] @ v[bh]  -> g_ao[b][s][h*64+d]
__global__ void av_kernel()
{
    __shared__ float sA[1024], sB[1024];
    int bh = blockIdx.z;
    int row0 = blockIdx.y * 64;
    float acc[4][4] = {};
    gemm64(g_att + ((size_t)bh * SS + row0) * SS, SS,
           g_v + (size_t)bh * SS * DH, DH, SS, acc, sA, sB);
    int tid = threadIdx.x, tx = tid & 15, ty = tid >> 4;
    int b = bh / HH, h = bh - b * HH;
#pragma unroll
    for (int i = 0; i < 4; i++) {
        int s = row0 + ty * 4 + i;
#pragma unroll
        for (int j = 0; j < 4; j++) {
            int d = tx * 4 + j;
            g_ao[((size_t)b * SS + s) * DD + h * DH + d] = acc[i][j];
        }
    }
}

// x2 = x + ao @ proj_w + proj_b
__global__ void proj_kernel(const float* __restrict__ W, const float* __restrict__ bias,
                            const float* __restrict__ x)
{
    __shared__ float sA[1024], sB[1024];
    int row0 = blockIdx.y * 64, col0 = blockIdx.x * 64;
    float acc[4][4] = {};
    gemm64(g_ao + (size_t)row0 * DD, DD, W + col0, DD, DD, acc, sA, sB);
    int tid = threadIdx.x, tx = tid & 15, ty = tid >> 4;
#pragma unroll
    for (int i = 0; i < 4; i++) {
        int m = row0 + ty * 4 + i;
#pragma unroll
        for (int j = 0; j < 4; j++) {
            int n = col0 + tx * 4 + j;
            size_t idx = (size_t)m * DD + n;
            g_x2[idx] = x[idx] + acc[i][j] + bias[n];
        }
    }
}

// seq_repr[b][d] = mean_s h2[b][s][d]
__global__ void seqmean_kernel()
{
    int b = blockIdx.y;
    int d = blockIdx.x * 256 + threadIdx.x;
    const float* p = g_h2 + (size_t)b * SS * DD + d;
    float s = 0.0f;
    for (int i = 0; i < SS; i++) s += p[(size_t)i * DD];
    g_seq[b * DD + d] = s * (1.0f / SS);
}

// router MLP + softmax + top-4 + renormalize -> g_wgt[b][e]
__global__ void router_kernel(const float* __restrict__ w1, const float* __restrict__ b1,
                              const float* __restrict__ w2, const float* __restrict__ b2)
{
    __shared__ float s_in[DD];
    __shared__ float s_hid[DD];
    __shared__ float s_logits[EE];
    int b = blockIdx.x;
    int tid = threadIdx.x;
    for (int i = tid; i < DD; i += 256) s_in[i] = g_seq[b * DD + i];
    __syncthreads();
    for (int j = tid; j < DD; j += 256) {
        float a = b1[j];
        for (int d = 0; d < DD; d++) a = fmaf(s_in[d], w1[(size_t)d * DD + j], a);
        s_hid[j] = geluf(a);
    }
    __syncthreads();
    if (tid < EE) {
        float a = b2[tid];
        for (int d = 0; d < DD; d++) a = fmaf(s_hid[d], w2[(size_t)d * EE + tid], a);
        s_logits[tid] = a;
    }
    __syncthreads();
    if (tid == 0) {
        float p[EE];
        float mx = -1e30f;
        for (int e = 0; e < EE; e++) mx = fmaxf(mx, s_logits[e]);
        float sum = 0.0f;
        for (int e = 0; e < EE; e++) { p[e] = expf(s_logits[e] - mx); sum += p[e]; }
        float inv = 1.0f / sum;
        for (int e = 0; e < EE; e++) p[e] *= inv;
        // top-4 (first-occurrence tie-break, like lax.top_k)
        int   idx[KK];
        float val[KK];
        bool used[EE] = {};
        for (int k = 0; k < KK; k++) {
            int best = -1; float bv = -1e30f;
            for (int e = 0; e < EE; e++)
                if (!used[e] && p[e] > bv) { bv = p[e]; best = e; }
            used[best] = true; idx[k] = best; val[k] = bv;
        }
        // renormalize via softmax over top-4 values
        float m2 = val[0];
        float s2 = 0.0f, tw[KK];
        for (int k = 0; k < KK; k++) { tw[k] = expf(val[k] - m2); s2 += tw[k]; }
        float inv2 = 1.0f / s2;
        for (int e = 0; e < EE; e++) g_wgt[b * EE + e] = 0.0f;
        for (int k = 0; k < KK; k++) g_wgt[b * EE + idx[k]] = tw[k] * inv2;
    }
}

// expert hidden: hid[e][b] = gelu(h2[b] @ w1[e] + b1[e]); skip zero-weight experts
__global__ void expert_hid_kernel(const float* __restrict__ w1, const float* __restrict__ b1)
{
    int z = blockIdx.z;
    int e = z >> 3, b = z & 7;
    if (g_wgt[b * EE + e] == 0.0f) return;
    __shared__ float sA[1024], sB[1024];
    int row0 = blockIdx.y * 64, col0 = blockIdx.x * 64;
    float acc[4][4] = {};
    gemm64(g_h2 + ((size_t)b * SS + row0) * DD, DD,
           w1 + (size_t)e * DD * HID + col0, HID, DD, acc, sA, sB);
    int tid = threadIdx.x, tx = tid & 15, ty = tid >> 4;
#pragma unroll
    for (int i = 0; i < 4; i++) {
        int row = row0 + ty * 4 + i;
#pragma unroll
        for (int j = 0; j < 4; j++) {
            int col = col0 + tx * 4 + j;
            g_ehid[(((size_t)e * BB + b) * SS + row) * HID + col] =
                geluf(acc[i][j] + b1[e * HID + col]);
        }
    }
}

// y[b] = sum_e wgt[b][e] * (hid[e][b] @ w2[e] + b2[e])
__global__ void expert_out_kernel(const float* __restrict__ w2, const float* __restrict__ b2)
{
    __shared__ float sA[1024], sB[1024];
    int b = blockIdx.z;
    int row0 = blockIdx.y * 64, col0 = blockIdx.x * 64;
    int tid = threadIdx.x, tx = tid & 15, ty = tid >> 4;
    float out[4][4] = {};
    for (int e = 0; e < EE; e++) {
        float w = g_wgt[b * EE + e];
        if (w == 0.0f) continue;
        float acc[4][4] = {};
        gemm64(g_ehid + (((size_t)e * BB + b) * SS + row0) * HID, HID,
               w2 + (size_t)e * HID * DD + col0, DD, HID, acc, sA, sB);
#pragma unroll
        for (int i = 0; i < 4; i++)
#pragma unroll
            for (int j = 0; j < 4; j++)
                out[i][j] += w * (acc[i][j] + b2[e * DD + col0 + tx * 4 + j]);
    }
#pragma unroll
    for (int i = 0; i < 4; i++) {
        int m = row0 + ty * 4 + i;
#pragma unroll
        for (int j = 0; j < 4; j++)
            g_y[(((size_t)b * SS + m) * DD) + col0 + tx * 4 + j] = out[i][j];
    }
}

// shared expert hidden: shid = gelu(h2 @ sh_w1 + sh_b1)
__global__ void shared_hid_kernel(const float* __restrict__ W, const float* __restrict__ b1)
{
    __shared__ float sA[1024], sB[1024];
    int row0 = blockIdx.y * 64, col0 = blockIdx.x * 64;
    float acc[4][4] = {};
    gemm64(g_h2 + (size_t)row0 * DD, DD, W + col0, SHH, DD, acc, sA, sB);
    int tid = threadIdx.x, tx = tid & 15, ty = tid >> 4;
#pragma unroll
    for (int i = 0; i < 4; i++) {
        int m = row0 + ty * 4 + i;
#pragma unroll
        for (int j = 0; j < 4; j++) {
            int n = col0 + tx * 4 + j;
            g_shid[(size_t)m * SHH + n] = geluf(acc[i][j] + b1[n]);
        }
    }
}

// out = x2 + y_experts + (shid @ sh_w2 + sh_b2)
__global__ void final_kernel(const float* __restrict__ W, const float* __restrict__ b2,
                             float* __restrict__ out)
{
    __shared__ float sA[1024], sB[1024];
    int row0 = blockIdx.y * 64, col0 = blockIdx.x * 64;
    float acc[4][4] = {};
    gemm64(g_shid + (size_t)row0 * SHH, SHH, W + col0, DD, SHH, acc, sA, sB);
    int tid = threadIdx.x, tx = tid & 15, ty = tid >> 4;
#pragma unroll
    for (int i = 0; i < 4; i++) {
        int m = row0 + ty * 4 + i;
#pragma unroll
        for (int j = 0; j < 4; j++) {
            int n = col0 + tx * 4 + j;
            size_t idx = (size_t)m * DD + n;
            out[idx] = g_x2[idx] + g_y[idx] + acc[i][j] + b2[n];
        }
    }
}

// ---------------- launch ----------------
extern "C" void kernel_launch(void* const* d_in, const int* in_sizes, int n_in,
                              void* d_out, int out_size)
{
    const float* x         = (const float*)d_in[0];
    const float* ln1_g     = (const float*)d_in[1];
    const float* ln1_b     = (const float*)d_in[2];
    const float* qkv_w     = (const float*)d_in[3];
    const float* proj_w    = (const float*)d_in[4];
    const float* proj_b    = (const float*)d_in[5];
    const float* ln2_g     = (const float*)d_in[6];
    const float* ln2_b     = (const float*)d_in[7];
    const float* router_w1 = (const float*)d_in[8];
    const float* router_b1 = (const float*)d_in[9];
    const float* router_w2 = (const float*)d_in[10];
    const float* router_b2 = (const float*)d_in[11];
    const float* exp_w1    = (const float*)d_in[12];
    const float* exp_b1    = (const float*)d_in[13];
    const float* exp_w2    = (const float*)d_in[14];
    const float* exp_b2    = (const float*)d_in[15];
    const float* sh_w1     = (const float*)d_in[16];
    const float* sh_b1     = (const float*)d_in[17];
    const float* sh_w2     = (const float*)d_in[18];
    const float* sh_b2     = (const float*)d_in[19];
    float* out = (float*)d_out;

    float* h1; cudaGetSymbolAddress((void**)&h1, g_h1);
    float* h2; cudaGetSymbolAddress((void**)&h2, g_h2);
    float* x2; cudaGetSymbolAddress((void**)&x2, g_x2);

    // attention branch
    ln_kernel<<<NTOK, 256>>>(x, ln1_g, ln1_b, h1);
    qkv_gemm_kernel<<<dim3(36, 64), 256>>>(qkv_w);
    attn_scores_kernel<<<dim3(8, 8, BHN), 256>>>();
    softmax_kernel<<<BHN * SS, 256>>>();
    av_kernel<<<dim3(1, 8, BHN), 256>>>();
    proj_kernel<<<dim3(12, 64), 256>>>(proj_w, proj_b, x);

    // MoE branch
    ln_kernel<<<NTOK, 256>>>(x2, ln2_g, ln2_b, h2);
    seqmean_kernel<<<dim3(3, BB), 256>>>();
    router_kernel<<<BB, 256>>>(router_w1, router_b1, router_w2, router_b2);
    expert_hid_kernel<<<dim3(24, 8, EE * BB), 256>>>(exp_w1, exp_b1);
    expert_out_kernel<<<dim3(12, 8, BB), 256>>>(exp_w2, exp_b2);
    shared_hid_kernel<<<dim3(48, 64), 256>>>(sh_w1, sh_b1);
    final_kernel<<<dim3(12, 64), 256>>>(sh_w2, sh_b2, out);
}

// round 2
// speedup vs baseline: 3.8709x; 3.8709x over previous
#include <cuda_runtime.h>
#include <cstdint>
#include <math.h>

// ---------------- problem constants ----------------
#define BB   8
#define SS   512
#define DD   768
#define HH   12
#define DH   64
#define EE   14
#define KK   4
#define HID  1536
#define SHH  3072
#define NTOK (BB*SS)          // 4096
#define BHN  (BB*HH)          // 96

// ---------------- scratch (device globals; no allocation) ----------------
__device__ float g_h1  [(size_t)NTOK*DD];
__device__ float g_q   [(size_t)BHN*SS*DH];
__device__ float g_k   [(size_t)BHN*SS*DH];
__device__ float g_v   [(size_t)BHN*SS*DH];
__device__ float g_att [(size_t)BHN*SS*SS];
__device__ float g_ao  [(size_t)NTOK*DD];
__device__ float g_x2  [(size_t)NTOK*DD];
__device__ float g_h2  [(size_t)NTOK*DD];
__device__ float g_seq [(size_t)BB*DD];
__device__ float g_wgt [(size_t)BB*EE];
__device__ float g_ehid[(size_t)EE*BB*SS*HID];
__device__ float g_y   [(size_t)NTOK*DD];
__device__ float g_shid[(size_t)NTOK*SHH];

// ---------------- helpers ----------------
__device__ __forceinline__ float geluf(float x) {
    return 0.5f * x * (1.0f + erff(x * 0.70710678118654752f));
}

__device__ __forceinline__ uint32_t f2tf32(float f) {
    uint32_t u;
    asm("cvt.rna.tf32.f32 %0, %1;" : "=r"(u) : "f"(f));
    return u;
}

__device__ __forceinline__ void ldsm4(uint32_t &r0, uint32_t &r1, uint32_t &r2, uint32_t &r3,
                                      uint32_t addr) {
    asm volatile("ldmatrix.sync.aligned.m8n8.x4.shared.b16 {%0,%1,%2,%3}, [%4];"
                 : "=r"(r0), "=r"(r1), "=r"(r2), "=r"(r3) : "r"(addr));
}

__device__ __forceinline__ void mma_tf32(float c[4], const uint32_t a[4], const uint32_t b[2]) {
    asm volatile("mma.sync.aligned.m16n8k8.row.col.f32.tf32.tf32.f32 "
                 "{%0,%1,%2,%3}, {%4,%5,%6,%7}, {%8,%9}, {%0,%1,%2,%3};"
                 : "+f"(c[0]), "+f"(c[1]), "+f"(c[2]), "+f"(c[3])
                 : "r"(a[0]), "r"(a[1]), "r"(a[2]), "r"(a[3]), "r"(b[0]), "r"(b[1]));
}

__device__ __forceinline__ float blockReduceSum(float v, float* sh) {
    int tid = threadIdx.x;
    sh[tid] = v; __syncthreads();
    for (int s = 128; s > 0; s >>= 1) {
        if (tid < s) sh[tid] += sh[tid + s];
        __syncthreads();
    }
    float r = sh[0]; __syncthreads();
    return r;
}

// ======================================================================
// tf32 tensor-core GEMM core.
// Block tile: 128 x (NT*16), BK=32, 256 threads = 8 warps (4 m x 2 n).
// Warp tile: 32 x (NT*8). Fragments via ldmatrix from padded smem (ld=36).
// A: global [M][K] row-major, pre-offset to block row origin, k=0.
// B: if BNK: global [N][K] row-major (attention K-matrix), pre-offset to
//    block col(row) origin;  else: global [K][N] row-major, pre-offset to col.
// acc accumulates (caller may call multiple times, e.g. summing experts);
// ascale scales A elements before tf32 conversion.
// ======================================================================
template<int NT, bool BNK>
__device__ __forceinline__ void gemm_tc(const float* __restrict__ A, int lda,
                                        const float* __restrict__ B, int ldb,
                                        int K, float ascale,
                                        uint32_t* sA, uint32_t* sB,
                                        float acc[2][NT][4])
{
    constexpr int BN = NT * 16;
    const int tid  = threadIdx.x;
    const int lane = tid & 31;
    const int w    = tid >> 5;
    const int wm   = w >> 1;
    const int wn   = w & 1;
    const int lr   = lane & 7;
    const int sub  = lane >> 3;

    const uint32_t sa0 = (uint32_t)__cvta_generic_to_shared(sA);
    const uint32_t sb0 = (uint32_t)__cvta_generic_to_shared(sB);

    // ldmatrix per-lane offsets
    const int a_row  = (sub & 1) * 8 + lr;   // within 16-row m-tile
    const int a_koff = (sub >> 1) * 4;
    const int b_row  = (sub >> 1) * 8 + lr;  // within 16-row n-pair
    const int b_koff = (sub & 1) * 4;

#pragma unroll 1
    for (int kt = 0; kt < K; kt += 32) {
        // ---- load A tile 128x32 (vectorized, convert to tf32) ----
#pragma unroll
        for (int i = 0; i < 4; i++) {
            int e = tid + i * 256;
            int row = e >> 3, v = e & 7;
            float4 f = *(const float4*)(A + (size_t)row * lda + kt + v * 4);
            uint4 u;
            u.x = f2tf32(f.x * ascale); u.y = f2tf32(f.y * ascale);
            u.z = f2tf32(f.z * ascale); u.w = f2tf32(f.w * ascale);
            *(uint4*)(sA + row * 36 + v * 4) = u;
        }
        // ---- load B tile -> sB[n][k] ----
        if (BNK) {
            // B stored [N][K] row-major: straight copy (BN==128 assumed)
#pragma unroll
            for (int i = 0; i < 4; i++) {
                int e = tid + i * 256;
                int row = e >> 3, v = e & 7;
                float4 f = *(const float4*)(B + (size_t)row * ldb + kt + v * 4);
                uint4 u;
                u.x = f2tf32(f.x); u.y = f2tf32(f.y);
                u.z = f2tf32(f.z); u.w = f2tf32(f.w);
                *(uint4*)(sB + row * 36 + v * 4) = u;
            }
        } else {
            // B stored [K][N] row-major: transpose into smem
#pragma unroll
            for (int i = 0; i < BN / 8; i++) {
                int e = tid + i * 256;
                int k = e / BN, n = e % BN;
                sB[n * 36 + k] = f2tf32(B[(size_t)(kt + k) * ldb + n]);
            }
        }
        __syncthreads();

        // ---- compute: 4 k-steps of 8 ----
#pragma unroll
        for (int kk = 0; kk < 4; kk++) {
            int k0 = kk * 8;
            uint32_t a[2][4];
#pragma unroll
            for (int mt = 0; mt < 2; mt++) {
                ldsm4(a[mt][0], a[mt][1], a[mt][2], a[mt][3],
                      sa0 + 4u * ((wm * 32 + mt * 16 + a_row) * 36 + k0 + a_koff));
            }
            uint32_t b[NT][2];
#pragma unroll
            for (int p = 0; p < NT / 2; p++) {
                uint32_t r0, r1, r2, r3;
                ldsm4(r0, r1, r2, r3,
                      sb0 + 4u * ((wn * NT * 8 + p * 16 + b_row) * 36 + k0 + b_koff));
                b[2 * p][0] = r0; b[2 * p][1] = r1;
                b[2 * p + 1][0] = r2; b[2 * p + 1][1] = r3;
            }
#pragma unroll
            for (int mt = 0; mt < 2; mt++)
#pragma unroll
                for (int nt = 0; nt < NT; nt++)
                    mma_tf32(acc[mt][nt], a[mt], b[nt]);
        }
        __syncthreads();
    }
}

// ---------------- elementwise kernels ----------------

__global__ void ln_kernel(const float* __restrict__ in, const float* __restrict__ g,
                          const float* __restrict__ b, float* __restrict__ out)
{
    __shared__ float red[256];
    size_t row = blockIdx.x;
    const float* xr = in + row * DD;
    int tid = threadIdx.x;
    float x0 = xr[tid], x1 = xr[tid + 256], x2 = xr[tid + 512];
    float total = blockReduceSum(x0 + x1 + x2, red);
    float mean = total * (1.0f / DD);
    float d0 = x0 - mean, d1 = x1 - mean, d2 = x2 - mean;
    float var = blockReduceSum(d0 * d0 + d1 * d1 + d2 * d2, red) * (1.0f / DD);
    float rstd = rsqrtf(var + 1e-5f);
    out[row * DD + tid]       = d0 * rstd * g[tid]       + b[tid];
    out[row * DD + tid + 256] = d1 * rstd * g[tid + 256] + b[tid + 256];
    out[row * DD + tid + 512] = d2 * rstd * g[tid + 512] + b[tid + 512];
}

__global__ void softmax_kernel()
{
    __shared__ float sh[256];
    size_t row = blockIdx.x;
    float* r = g_att + row * SS;
    int tid = threadIdx.x;
    float a = r[tid], b = r[tid + 256];
    sh[tid] = fmaxf(a, b); __syncthreads();
    for (int s = 128; s > 0; s >>= 1) {
        if (tid < s) sh[tid] = fmaxf(sh[tid], sh[tid + s]);
        __syncthreads();
    }
    float mx = sh[0]; __syncthreads();
    a = expf(a - mx); b = expf(b - mx);
    float total = blockReduceSum(a + b, sh);
    float inv = 1.0f / total;
    r[tid] = a * inv;
    r[tid + 256] = b * inv;
}

__global__ void seqmean_kernel()
{
    int b = blockIdx.y;
    int d = blockIdx.x * 256 + threadIdx.x;
    const float* p = g_h2 + (size_t)b * SS * DD + d;
    float s = 0.0f;
    for (int i = 0; i < SS; i++) s += p[(size_t)i * DD];
    g_seq[b * DD + d] = s * (1.0f / SS);
}

__global__ void router_kernel(const float* __restrict__ w1, const float* __restrict__ b1,
                              const float* __restrict__ w2, const float* __restrict__ b2)
{
    __shared__ float s_in[DD];
    __shared__ float s_hid[DD];
    __shared__ float s_logits[EE];
    int b = blockIdx.x;
    int tid = threadIdx.x;
    for (int i = tid; i < DD; i += 256) s_in[i] = g_seq[b * DD + i];
    __syncthreads();
    for (int j = tid; j < DD; j += 256) {
        float a = b1[j];
        for (int d = 0; d < DD; d++) a = fmaf(s_in[d], w1[(size_t)d * DD + j], a);
        s_hid[j] = geluf(a);
    }
    __syncthreads();
    if (tid < EE) {
        float a = b2[tid];
        for (int d = 0; d < DD; d++) a = fmaf(s_hid[d], w2[(size_t)d * EE + tid], a);
        s_logits[tid] = a;
    }
    __syncthreads();
    if (tid == 0) {
        float p[EE];
        float mx = -1e30f;
        for (int e = 0; e < EE; e++) mx = fmaxf(mx, s_logits[e]);
        float sum = 0.0f;
        for (int e = 0; e < EE; e++) { p[e] = expf(s_logits[e] - mx); sum += p[e]; }
        float inv = 1.0f / sum;
        for (int e = 0; e < EE; e++) p[e] *= inv;
        int   idx[KK];
        float val[KK];
        bool used[EE] = {};
        for (int k = 0; k < KK; k++) {
            int best = -1; float bv = -1e30f;
            for (int e = 0; e < EE; e++)
                if (!used[e] && p[e] > bv) { bv = p[e]; best = e; }
            used[best] = true; idx[k] = best; val[k] = bv;
        }
        float m2 = val[0];
        float s2 = 0.0f, tw[KK];
        for (int k = 0; k < KK; k++) { tw[k] = expf(val[k] - m2); s2 += tw[k]; }
        float inv2 = 1.0f / s2;
        for (int e = 0; e < EE; e++) g_wgt[b * EE + e] = 0.0f;
        for (int k = 0; k < KK; k++) g_wgt[b * EE + idx[k]] = tw[k] * inv2;
    }
}

// ---------------- tensor-core GEMM kernels ----------------
// Common epilogue indexing: lane g = lane>>2, tig = lane&3.
// element (mt,nt,c0/c1) -> row0 + wm*32 + mt*16 + g (+8 for c2/c3),
//                          col0 + wn*NT*8 + nt*8 + 2*tig (+1)

#define EPI_SETUP()                                             \
    const int tid = threadIdx.x;                                \
    const int lane = tid & 31, w = tid >> 5;                    \
    const int wm = w >> 1, wn = w & 1;                          \
    const int g = lane >> 2, tig = lane & 3;

// QKV: [4096,768] @ [768,2304] -> scatter q/k/v [B,H,S,dh]
__global__ void qkv_tc(const float* __restrict__ W)
{
    __shared__ uint32_t sA[128 * 36], sB[128 * 36];
    int row0 = blockIdx.y * 128, col0 = blockIdx.x * 128;
    float acc[2][8][4] = {};
    gemm_tc<8, false>(g_h1 + (size_t)row0 * DD, DD, W + col0, 3 * DD, DD, 1.0f, sA, sB, acc);
    EPI_SETUP();
#pragma unroll
    for (int mt = 0; mt < 2; mt++)
#pragma unroll
        for (int nt = 0; nt < 8; nt++) {
            int n = col0 + wn * 64 + nt * 8 + 2 * tig;
            int which = n / DD;
            int rem = n - which * DD;
            int h = rem >> 6, d = rem & 63;
            float* dst = (which == 0) ? g_q : ((which == 1) ? g_k : g_v);
#pragma unroll
            for (int half = 0; half < 2; half++) {
                int m = row0 + wm * 32 + mt * 16 + g + half * 8;
                int b = m >> 9, s = m & 511;
                float2 v2 = make_float2(acc[mt][nt][2 * half], acc[mt][nt][2 * half + 1]);
                *(float2*)&dst[(((size_t)b * HH + h) * SS + s) * DH + d] = v2;
            }
        }
}

// attention scores: Q[512,64] @ K^T -> att, scaled
__global__ void attn_scores_tc()
{
    __shared__ uint32_t sA[128 * 36], sB[128 * 36];
    int bh = blockIdx.z;
    int row0 = blockIdx.y * 128, col0 = blockIdx.x * 128;
    float acc[2][8][4] = {};
    gemm_tc<8, true>(g_q + ((size_t)bh * SS + row0) * DH, DH,
                     g_k + ((size_t)bh * SS + col0) * DH, DH, DH, 1.0f, sA, sB, acc);
    EPI_SETUP();
    float* out = g_att + (size_t)bh * SS * SS;
#pragma unroll
    for (int mt = 0; mt < 2; mt++)
#pragma unroll
        for (int nt = 0; nt < 8; nt++) {
            int n = col0 + wn * 64 + nt * 8 + 2 * tig;
#pragma unroll
            for (int half = 0; half < 2; half++) {
                int m = row0 + wm * 32 + mt * 16 + g + half * 8;
                float2 v2 = make_float2(acc[mt][nt][2 * half] * 0.125f,
                                        acc[mt][nt][2 * half + 1] * 0.125f);
                *(float2*)&out[(size_t)m * SS + n] = v2;
            }
        }
}

// AV: att[512,512] @ V[512,64] -> g_ao (scatter heads)
__global__ void av_tc()
{
    __shared__ uint32_t sA[128 * 36], sB[64 * 36];
    int bh = blockIdx.z;
    int row0 = blockIdx.y * 128;
    float acc[2][4][4] = {};
    gemm_tc<4, false>(g_att + ((size_t)bh * SS + row0) * SS, SS,
                      g_v + (size_t)bh * SS * DH, DH, SS, 1.0f, sA, sB, acc);
    EPI_SETUP();
    int b = bh / HH, h = bh - b * HH;
#pragma unroll
    for (int mt = 0; mt < 2; mt++)
#pragma unroll
        for (int nt = 0; nt < 4; nt++) {
            int d = wn * 32 + nt * 8 + 2 * tig;
#pragma unroll
            for (int half = 0; half < 2; half++) {
                int s = row0 + wm * 32 + mt * 16 + g + half * 8;
                float2 v2 = make_float2(acc[mt][nt][2 * half], acc[mt][nt][2 * half + 1]);
                *(float2*)&g_ao[((size_t)b * SS + s) * DD + h * DH + d] = v2;
            }
        }
}

// proj: x2 = x + ao @ proj_w + proj_b
__global__ void proj_tc(const float* __restrict__ W, const float* __restrict__ bias,
                        const float* __restrict__ x)
{
    __shared__ uint32_t sA[128 * 36], sB[128 * 36];
    int row0 = blockIdx.y * 128, col0 = blockIdx.x * 128;
    float acc[2][8][4] = {};
    gemm_tc<8, false>(g_ao + (size_t)row0 * DD, DD, W + col0, DD, DD, 1.0f, sA, sB, acc);
    EPI_SETUP();
#pragma unroll
    for (int mt = 0; mt < 2; mt++)
#pragma unroll
        for (int nt = 0; nt < 8; nt++) {
            int n = col0 + wn * 64 + nt * 8 + 2 * tig;
            float b0 = bias[n], b1 = bias[n + 1];
#pragma unroll
            for (int half = 0; half < 2; half++) {
                int m = row0 + wm * 32 + mt * 16 + g + half * 8;
                size_t idx = (size_t)m * DD + n;
                float2 xv = *(const float2*)&x[idx];
                float2 v2 = make_float2(xv.x + acc[mt][nt][2 * half] + b0,
                                        xv.y + acc[mt][nt][2 * half + 1] + b1);
                *(float2*)&g_x2[idx] = v2;
            }
        }
}

// expert hidden: gelu(h2[b] @ w1[e] + b1[e]); skip zero-weight experts
__global__ void expert_hid_tc(const float* __restrict__ w1, const float* __restrict__ b1)
{
    int z = blockIdx.z;
    int e = z >> 3, b = z & 7;
    if (g_wgt[b * EE + e] == 0.0f) return;
    __shared__ uint32_t sA[128 * 36], sB[128 * 36];
    int row0 = blockIdx.y * 128, col0 = blockIdx.x * 128;
    float acc[2][8][4] = {};
    gemm_tc<8, false>(g_h2 + ((size_t)b * SS + row0) * DD, DD,
                      w1 + (size_t)e * DD * HID + col0, HID, DD, 1.0f, sA, sB, acc);
    EPI_SETUP();
    float* dst = g_ehid + ((size_t)e * BB + b) * SS * HID;
#pragma unroll
    for (int mt = 0; mt < 2; mt++)
#pragma unroll
        for (int nt = 0; nt < 8; nt++) {
            int n = col0 + wn * 64 + nt * 8 + 2 * tig;
            float b0 = b1[e * HID + n], bx = b1[e * HID + n + 1];
#pragma unroll
            for (int half = 0; half < 2; half++) {
                int m = row0 + wm * 32 + mt * 16 + g + half * 8;
                float2 v2 = make_float2(geluf(acc[mt][nt][2 * half] + b0),
                                        geluf(acc[mt][nt][2 * half + 1] + bx));
                *(float2*)&dst[(size_t)m * HID + n] = v2;
            }
        }
}

// expert out: y[b] = sum_e w_e * (hid[e][b] @ w2[e] + b2[e])
// weight folded into A via ascale; bias summed in smem.
__global__ void expert_out_tc(const float* __restrict__ w2, const float* __restrict__ b2)
{
    __shared__ uint32_t sA[128 * 36], sB[128 * 36];
    __shared__ float s_bias[128];
    int b = blockIdx.z;
    int row0 = blockIdx.y * 128, col0 = blockIdx.x * 128;
    float acc[2][8][4] = {};
    for (int e = 0; e < EE; e++) {
        float wv = g_wgt[b * EE + e];
        if (wv == 0.0f) continue;
        gemm_tc<8, false>(g_ehid + (((size_t)e * BB + b) * SS + row0) * HID, HID,
                          w2 + (size_t)e * HID * DD + col0, DD, HID, wv, sA, sB, acc);
    }
    // summed weighted bias for this column block
    if (threadIdx.x < 128) {
        float s = 0.0f;
        for (int e = 0; e < EE; e++)
            s += g_wgt[b * EE + e] * b2[e * DD + col0 + threadIdx.x];
        s_bias[threadIdx.x] = s;
    }
    __syncthreads();
    EPI_SETUP();
#pragma unroll
    for (int mt = 0; mt < 2; mt++)
#pragma unroll
        for (int nt = 0; nt < 8; nt++) {
            int nl = wn * 64 + nt * 8 + 2 * tig;
            float b0 = s_bias[nl], b1v = s_bias[nl + 1];
#pragma unroll
            for (int half = 0; half < 2; half++) {
                int m = row0 + wm * 32 + mt * 16 + g + half * 8;
                float2 v2 = make_float2(acc[mt][nt][2 * half] + b0,
                                        acc[mt][nt][2 * half + 1] + b1v);
                *(float2*)&g_y[((size_t)b * SS + m) * DD + col0 + nl] = v2;
            }
        }
}

// shared expert hidden: shid = gelu(h2 @ sh_w1 + sh_b1)
__global__ void shared_hid_tc(const float* __restrict__ W, const float* __restrict__ b1)
{
    __shared__ uint32_t sA[128 * 36], sB[128 * 36];
    int row0 = blockIdx.y * 128, col0 = blockIdx.x * 128;
    float acc[2][8][4] = {};
    gemm_tc<8, false>(g_h2 + (size_t)row0 * DD, DD, W + col0, SHH, DD, 1.0f, sA, sB, acc);
    EPI_SETUP();
#pragma unroll
    for (int mt = 0; mt < 2; mt++)
#pragma unroll
        for (int nt = 0; nt < 8; nt++) {
            int n = col0 + wn * 64 + nt * 8 + 2 * tig;
            float b0 = b1[n], bx = b1[n + 1];
#pragma unroll
            for (int half = 0; half < 2; half++) {
                int m = row0 + wm * 32 + mt * 16 + g + half * 8;
                float2 v2 = make_float2(geluf(acc[mt][nt][2 * half] + b0),
                                        geluf(acc[mt][nt][2 * half + 1] + bx));
                *(float2*)&g_shid[(size_t)m * SHH + n] = v2;
            }
        }
}

// out = x2 + y + shid @ sh_w2 + sh_b2
__global__ void final_tc(const float* __restrict__ W, const float* __restrict__ b2,
                         float* __restrict__ out)
{
    __shared__ uint32_t sA[128 * 36], sB[128 * 36];
    int row0 = blockIdx.y * 128, col0 = blockIdx.x * 128;
    float acc[2][8][4] = {};
    gemm_tc<8, false>(g_shid + (size_t)row0 * SHH, SHH, W + col0, DD, SHH, 1.0f, sA, sB, acc);
    EPI_SETUP();
#pragma unroll
    for (int mt = 0; mt < 2; mt++)
#pragma unroll
        for (int nt = 0; nt < 8; nt++) {
            int n = col0 + wn * 64 + nt * 8 + 2 * tig;
            float b0 = b2[n], bx = b2[n + 1];
#pragma unroll
            for (int half = 0; half < 2; half++) {
                int m = row0 + wm * 32 + mt * 16 + g + half * 8;
                size_t idx = (size_t)m * DD + n;
                float2 xv = *(const float2*)&g_x2[idx];
                float2 yv = *(const float2*)&g_y[idx];
                float2 v2 = make_float2(xv.x + yv.x + acc[mt][nt][2 * half] + b0,
                                        xv.y + yv.y + acc[mt][nt][2 * half + 1] + bx);
                *(float2*)&out[idx] = v2;
            }
        }
}

// ---------------- launch ----------------
extern "C" void kernel_launch(void* const* d_in, const int* in_sizes, int n_in,
                              void* d_out, int out_size)
{
    const float* x         = (const float*)d_in[0];
    const float* ln1_g     = (const float*)d_in[1];
    const float* ln1_b     = (const float*)d_in[2];
    const float* qkv_w     = (const float*)d_in[3];
    const float* proj_w    = (const float*)d_in[4];
    const float* proj_b    = (const float*)d_in[5];
    const float* ln2_g     = (const float*)d_in[6];
    const float* ln2_b     = (const float*)d_in[7];
    const float* router_w1 = (const float*)d_in[8];
    const float* router_b1 = (const float*)d_in[9];
    const float* router_w2 = (const float*)d_in[10];
    const float* router_b2 = (const float*)d_in[11];
    const float* exp_w1    = (const float*)d_in[12];
    const float* exp_b1    = (const float*)d_in[13];
    const float* exp_w2    = (const float*)d_in[14];
    const float* exp_b2    = (const float*)d_in[15];
    const float* sh_w1     = (const float*)d_in[16];
    const float* sh_b1     = (const float*)d_in[17];
    const float* sh_w2     = (const float*)d_in[18];
    const float* sh_b2     = (const float*)d_in[19];
    float* out = (float*)d_out;

    float* h1; cudaGetSymbolAddress((void**)&h1, g_h1);
    float* h2; cudaGetSymbolAddress((void**)&h2, g_h2);
    float* x2; cudaGetSymbolAddress((void**)&x2, g_x2);

    // attention branch
    ln_kernel<<<NTOK, 256>>>(x, ln1_g, ln1_b, h1);
    qkv_tc<<<dim3(18, 32), 256>>>(qkv_w);
    attn_scores_tc<<<dim3(4, 4, BHN), 256>>>();
    softmax_kernel<<<BHN * SS, 256>>>();
    av_tc<<<dim3(1, 4, BHN), 256>>>();
    proj_tc<<<dim3(6, 32), 256>>>(proj_w, proj_b, x);

    // MoE branch
    ln_kernel<<<NTOK, 256>>>(x2, ln2_g, ln2_b, h2);
    seqmean_kernel<<<dim3(3, BB), 256>>>();
    router_kernel<<<BB, 256>>>(router_w1, router_b1, router_w2, router_b2);
    expert_hid_tc<<<dim3(12, 4, EE * BB), 256>>>(exp_w1, exp_b1);
    expert_out_tc<<<dim3(6, 4, BB), 256>>>(exp_w2, exp_b2);
    shared_hid_tc<<<dim3(24, 32), 256>>>(sh_w1, sh_b1);
    final_tc<<<dim3(6, 32), 256>>>(sh_w2, sh_b2, out);
}

// round 3
// speedup vs baseline: 5.0221x; 1.2974x over previous
#include <cuda_runtime.h>
#include <cstdint>
#include <math.h>

// ---------------- problem constants ----------------
#define BB   8
#define SS   512
#define DD   768
#define HH   12
#define DH   64
#define EE   14
#define KK   4
#define HID  1536
#define SHH  3072
#define NTOK (BB*SS)          // 4096
#define BHN  (BB*HH)          // 96

// ---------------- scratch (device globals; no allocation) ----------------
__device__ float g_h1  [(size_t)NTOK*DD];
__device__ float g_q   [(size_t)BHN*SS*DH];
__device__ float g_k   [(size_t)BHN*SS*DH];
__device__ float g_v   [(size_t)BHN*SS*DH];
__device__ float g_att [(size_t)BHN*SS*SS];
__device__ float g_ao  [(size_t)NTOK*DD];
__device__ float g_x2  [(size_t)NTOK*DD];
__device__ float g_h2  [(size_t)NTOK*DD];
__device__ float g_seq [(size_t)BB*DD];
__device__ float g_wgt [(size_t)BB*EE];
__device__ float g_ehid[(size_t)EE*BB*SS*HID];
__device__ float g_y   [(size_t)NTOK*DD];
__device__ float g_shid[(size_t)NTOK*SHH];

// ---------------- helpers ----------------
__device__ __forceinline__ float geluf(float x) {
    return 0.5f * x * (1.0f + erff(x * 0.70710678118654752f));
}

__device__ __forceinline__ void ldsm4(uint32_t &r0, uint32_t &r1, uint32_t &r2, uint32_t &r3,
                                      uint32_t addr) {
    asm volatile("ldmatrix.sync.aligned.m8n8.x4.shared.b16 {%0,%1,%2,%3}, [%4];"
                 : "=r"(r0), "=r"(r1), "=r"(r2), "=r"(r3) : "r"(addr));
}

__device__ __forceinline__ void mma_tf32(float c[4], const uint32_t a[4], const uint32_t b[2]) {
    asm volatile("mma.sync.aligned.m16n8k8.row.col.f32.tf32.tf32.f32 "
                 "{%0,%1,%2,%3}, {%4,%5,%6,%7}, {%8,%9}, {%0,%1,%2,%3};"
                 : "+f"(c[0]), "+f"(c[1]), "+f"(c[2]), "+f"(c[3])
                 : "r"(a[0]), "r"(a[1]), "r"(a[2]), "r"(a[3]), "r"(b[0]), "r"(b[1]));
}

__device__ __forceinline__ void cp16(float* dst_smem, const float* src) {
    uint32_t d = (uint32_t)__cvta_generic_to_shared(dst_smem);
    asm volatile("cp.async.cg.shared.global [%0], [%1], 16;" :: "r"(d), "l"(src));
}

__device__ __forceinline__ float blockReduceSum(float v, float* sh) {
    int tid = threadIdx.x;
    sh[tid] = v; __syncthreads();
    for (int s = 128; s > 0; s >>= 1) {
        if (tid < s) sh[tid] += sh[tid + s];
        __syncthreads();
    }
    float r = sh[0]; __syncthreads();
    return r;
}

// ======================================================================
// tf32 tensor-core GEMM core, v2: cp.async double-buffered, no cvt
// (raw fp32 bits are valid tf32 operands; HW uses top 19 bits).
// Block tile: 128 x (NT*16), BK=32, 256 threads = 8 warps (4m x 2n).
// Warp tile: 32 x (NT*8).
// A: global [M][K] row-major (pre-offset), smem [m][k] stride 36, ldmatrix.
// B (BNK=true):  global [N][K] row-major, smem [n][k] stride 36, ldmatrix.
// B (BNK=false): global [K][N] row-major, smem [k][n] stride LDB, LDS.32.
// acc accumulates across calls.
// ======================================================================
template<int NT, bool BNK>
__device__ __forceinline__ void gemm_tc2(const float* __restrict__ A, int lda,
                                         const float* __restrict__ B, int ldb,
                                         int K, float* smem, float acc[2][NT][4])
{
    constexpr int BN  = NT * 16;
    constexpr int LDB = BNK ? 36 : (BN == 128 ? 136 : 72);
    constexpr int ASZ = 128 * 36;
    constexpr int BSZ = BNK ? (BN * 36) : (32 * LDB);

    float* sA0 = smem;
    float* sA1 = smem + ASZ;
    float* sB0 = smem + 2 * ASZ;
    float* sB1 = smem + 2 * ASZ + BSZ;

    const int tid  = threadIdx.x;
    const int lane = tid & 31;
    const int w    = tid >> 5;
    const int wm   = w >> 1;
    const int wn   = w & 1;
    const int lr   = lane & 7;
    const int sub  = lane >> 3;
    const int a_row  = (sub & 1) * 8 + lr;
    const int a_koff = (sub >> 1) * 4;
    const int b_row  = (sub >> 1) * 8 + lr;
    const int b_koff = (sub & 1) * 4;
    const int bk = lane & 3;
    const int bg = lane >> 2;

#define LOAD_A(kt, dst)                                                     \
    {                                                                       \
        _Pragma("unroll")                                                   \
        for (int i = 0; i < 4; i++) {                                       \
            int e = tid + i * 256;                                          \
            int row = e >> 3, v = e & 7;                                    \
            cp16((dst) + row * 36 + v * 4, A + (size_t)row * lda + (kt) + v * 4); \
        }                                                                   \
    }
#define LOAD_B(kt, dst)                                                     \
    {                                                                       \
        if (BNK) {                                                          \
            _Pragma("unroll")                                               \
            for (int i = 0; i < BN / 32; i++) {                             \
                int e = tid + i * 256;                                      \
                int row = e >> 3, v = e & 7;                                \
                cp16((dst) + row * 36 + v * 4, B + (size_t)row * ldb + (kt) + v * 4); \
            }                                                               \
        } else {                                                            \
            _Pragma("unroll")                                               \
            for (int i = 0; i < BN / 32; i++) {                             \
                int e = tid + i * 256;                                      \
                int row = e / (BN / 4), v = e % (BN / 4);                   \
                cp16((dst) + row * LDB + v * 4, B + (size_t)((kt) + row) * ldb + v * 4); \
            }                                                               \
        }                                                                   \
    }

    const int nst = K / 32;
    LOAD_A(0, sA0); LOAD_B(0, sB0);
    asm volatile("cp.async.commit_group;");

    for (int t = 0; t < nst; t++) {
        float* cA = (t & 1) ? sA1 : sA0;
        float* cB = (t & 1) ? sB1 : sB0;
        if (t + 1 < nst) {
            float* nA = (t & 1) ? sA0 : sA1;
            float* nB = (t & 1) ? sB0 : sB1;
            int kt = (t + 1) * 32;
            LOAD_A(kt, nA); LOAD_B(kt, nB);
            asm volatile("cp.async.commit_group;");
            asm volatile("cp.async.wait_group 1;" ::: "memory");
        } else {
            asm volatile("cp.async.wait_group 0;" ::: "memory");
        }
        __syncthreads();

        uint32_t sa0 = (uint32_t)__cvta_generic_to_shared(cA);
        uint32_t sb0 = (uint32_t)__cvta_generic_to_shared(cB);
#pragma unroll
        for (int kk = 0; kk < 4; kk++) {
            int k0 = kk * 8;
            uint32_t a[2][4];
#pragma unroll
            for (int mt = 0; mt < 2; mt++) {
                ldsm4(a[mt][0], a[mt][1], a[mt][2], a[mt][3],
                      sa0 + 4u * ((wm * 32 + mt * 16 + a_row) * 36 + k0 + a_koff));
            }
            uint32_t b[NT][2];
            if (BNK) {
#pragma unroll
                for (int p = 0; p < NT / 2; p++) {
                    uint32_t r0, r1, r2, r3;
                    ldsm4(r0, r1, r2, r3,
                          sb0 + 4u * ((wn * NT * 8 + p * 16 + b_row) * 36 + k0 + b_koff));
                    b[2 * p][0] = r0; b[2 * p][1] = r1;
                    b[2 * p + 1][0] = r2; b[2 * p + 1][1] = r3;
                }
            } else {
                const float* base0 = cB + (k0 + bk) * LDB + wn * NT * 8 + bg;
#pragma unroll
                for (int nt = 0; nt < NT; nt++) {
                    b[nt][0] = __float_as_uint(base0[nt * 8]);
                    b[nt][1] = __float_as_uint(base0[nt * 8 + 4 * LDB]);
                }
            }
#pragma unroll
            for (int mt = 0; mt < 2; mt++)
#pragma unroll
                for (int nt = 0; nt < NT; nt++)
                    mma_tf32(acc[mt][nt], a[mt], b[nt]);
        }
        __syncthreads();
    }
#undef LOAD_A
#undef LOAD_B
}

// smem byte sizes for the three shapes
#define SMEMB_STD  ((2*128*36 + 2*32*136) * 4)   // 71680
#define SMEMB_BNK  ((2*128*36 + 2*128*36) * 4)   // 73728
#define SMEMB_AV   ((2*128*36 + 2*32*72)  * 4)   // 55296

// ---------------- elementwise kernels ----------------

__global__ void ln_kernel(const float* __restrict__ in, const float* __restrict__ g,
                          const float* __restrict__ b, float* __restrict__ out)
{
    __shared__ float red[256];
    size_t row = blockIdx.x;
    const float* xr = in + row * DD;
    int tid = threadIdx.x;
    float x0 = xr[tid], x1 = xr[tid + 256], x2 = xr[tid + 512];
    float total = blockReduceSum(x0 + x1 + x2, red);
    float mean = total * (1.0f / DD);
    float d0 = x0 - mean, d1 = x1 - mean, d2 = x2 - mean;
    float var = blockReduceSum(d0 * d0 + d1 * d1 + d2 * d2, red) * (1.0f / DD);
    float rstd = rsqrtf(var + 1e-5f);
    out[row * DD + tid]       = d0 * rstd * g[tid]       + b[tid];
    out[row * DD + tid + 256] = d1 * rstd * g[tid + 256] + b[tid + 256];
    out[row * DD + tid + 512] = d2 * rstd * g[tid + 512] + b[tid + 512];
}

__global__ void softmax_kernel()
{
    __shared__ float sh[256];
    size_t row = blockIdx.x;
    float* r = g_att + row * SS;
    int tid = threadIdx.x;
    float a = r[tid], b = r[tid + 256];
    sh[tid] = fmaxf(a, b); __syncthreads();
    for (int s = 128; s > 0; s >>= 1) {
        if (tid < s) sh[tid] = fmaxf(sh[tid], sh[tid + s]);
        __syncthreads();
    }
    float mx = sh[0]; __syncthreads();
    a = __expf(a - mx); b = __expf(b - mx);
    float total = blockReduceSum(a + b, sh);
    float inv = 1.0f / total;
    r[tid] = a * inv;
    r[tid + 256] = b * inv;
}

__global__ void seqmean_kernel()
{
    int b = blockIdx.y;
    int d = blockIdx.x * 256 + threadIdx.x;
    const float* p = g_h2 + (size_t)b * SS * DD + d;
    float s = 0.0f;
    for (int i = 0; i < SS; i++) s += p[(size_t)i * DD];
    g_seq[b * DD + d] = s * (1.0f / SS);
}

__global__ void router_kernel(const float* __restrict__ w1, const float* __restrict__ b1,
                              const float* __restrict__ w2, const float* __restrict__ b2)
{
    __shared__ float s_in[DD];
    __shared__ float s_hid[DD];
    __shared__ float s_logits[EE];
    int b = blockIdx.x;
    int tid = threadIdx.x;
    for (int i = tid; i < DD; i += 256) s_in[i] = g_seq[b * DD + i];
    __syncthreads();
    for (int j = tid; j < DD; j += 256) {
        float a = b1[j];
        for (int d = 0; d < DD; d++) a = fmaf(s_in[d], w1[(size_t)d * DD + j], a);
        s_hid[j] = geluf(a);
    }
    __syncthreads();
    if (tid < EE) {
        float a = b2[tid];
        for (int d = 0; d < DD; d++) a = fmaf(s_hid[d], w2[(size_t)d * EE + tid], a);
        s_logits[tid] = a;
    }
    __syncthreads();
    if (tid == 0) {
        float p[EE];
        float mx = -1e30f;
        for (int e = 0; e < EE; e++) mx = fmaxf(mx, s_logits[e]);
        float sum = 0.0f;
        for (int e = 0; e < EE; e++) { p[e] = expf(s_logits[e] - mx); sum += p[e]; }
        float inv = 1.0f / sum;
        for (int e = 0; e < EE; e++) p[e] *= inv;
        int   idx[KK];
        float val[KK];
        bool used[EE] = {};
        for (int k = 0; k < KK; k++) {
            int best = -1; float bv = -1e30f;
            for (int e = 0; e < EE; e++)
                if (!used[e] && p[e] > bv) { bv = p[e]; best = e; }
            used[best] = true; idx[k] = best; val[k] = bv;
        }
        float m2 = val[0];
        float s2 = 0.0f, tw[KK];
        for (int k = 0; k < KK; k++) { tw[k] = expf(val[k] - m2); s2 += tw[k]; }
        float inv2 = 1.0f / s2;
        for (int e = 0; e < EE; e++) g_wgt[b * EE + e] = 0.0f;
        for (int k = 0; k < KK; k++) g_wgt[b * EE + idx[k]] = tw[k] * inv2;
    }
}

// ---------------- tensor-core GEMM kernels ----------------

#define EPI_SETUP()                                             \
    const int tid = threadIdx.x;                                \
    const int lane = tid & 31, w = tid >> 5;                    \
    const int wm = w >> 1, wn = w & 1;                          \
    const int g = lane >> 2, tig = lane & 3;

// QKV: [4096,768] @ [768,2304] -> scatter q/k/v [B,H,S,dh]
__global__ void qkv_tc(const float* __restrict__ W)
{
    extern __shared__ float smem[];
    int row0 = blockIdx.y * 128, col0 = blockIdx.x * 128;
    float acc[2][8][4] = {};
    gemm_tc2<8, false>(g_h1 + (size_t)row0 * DD, DD, W + col0, 3 * DD, DD, smem, acc);
    EPI_SETUP();
#pragma unroll
    for (int mt = 0; mt < 2; mt++)
#pragma unroll
        for (int nt = 0; nt < 8; nt++) {
            int n = col0 + wn * 64 + nt * 8 + 2 * tig;
            int which = n / DD;
            int rem = n - which * DD;
            int h = rem >> 6, d = rem & 63;
            float* dst = (which == 0) ? g_q : ((which == 1) ? g_k : g_v);
#pragma unroll
            for (int half = 0; half < 2; half++) {
                int m = row0 + wm * 32 + mt * 16 + g + half * 8;
                int b = m >> 9, s = m & 511;
                float2 v2 = make_float2(acc[mt][nt][2 * half], acc[mt][nt][2 * half + 1]);
                *(float2*)&dst[(((size_t)b * HH + h) * SS + s) * DH + d] = v2;
            }
        }
}

// attention scores: Q[512,64] @ K^T -> att, scaled
__global__ void attn_scores_tc()
{
    extern __shared__ float smem[];
    int bh = blockIdx.z;
    int row0 = blockIdx.y * 128, col0 = blockIdx.x * 128;
    float acc[2][8][4] = {};
    gemm_tc2<8, true>(g_q + ((size_t)bh * SS + row0) * DH, DH,
                      g_k + ((size_t)bh * SS + col0) * DH, DH, DH, smem, acc);
    EPI_SETUP();
    float* out = g_att + (size_t)bh * SS * SS;
#pragma unroll
    for (int mt = 0; mt < 2; mt++)
#pragma unroll
        for (int nt = 0; nt < 8; nt++) {
            int n = col0 + wn * 64 + nt * 8 + 2 * tig;
#pragma unroll
            for (int half = 0; half < 2; half++) {
                int m = row0 + wm * 32 + mt * 16 + g + half * 8;
                float2 v2 = make_float2(acc[mt][nt][2 * half] * 0.125f,
                                        acc[mt][nt][2 * half + 1] * 0.125f);
                *(float2*)&out[(size_t)m * SS + n] = v2;
            }
        }
}

// AV: att[512,512] @ V[512,64] -> g_ao (scatter heads)
__global__ void av_tc()
{
    extern __shared__ float smem[];
    int bh = blockIdx.z;
    int row0 = blockIdx.y * 128;
    float acc[2][4][4] = {};
    gemm_tc2<4, false>(g_att + ((size_t)bh * SS + row0) * SS, SS,
                       g_v + (size_t)bh * SS * DH, DH, SS, smem, acc);
    EPI_SETUP();
    int b = bh / HH, h = bh - b * HH;
#pragma unroll
    for (int mt = 0; mt < 2; mt++)
#pragma unroll
        for (int nt = 0; nt < 4; nt++) {
            int d = wn * 32 + nt * 8 + 2 * tig;
#pragma unroll
            for (int half = 0; half < 2; half++) {
                int s = row0 + wm * 32 + mt * 16 + g + half * 8;
                float2 v2 = make_float2(acc[mt][nt][2 * half], acc[mt][nt][2 * half + 1]);
                *(float2*)&g_ao[((size_t)b * SS + s) * DD + h * DH + d] = v2;
            }
        }
}

// proj: x2 = x + ao @ proj_w + proj_b
__global__ void proj_tc(const float* __restrict__ W, const float* __restrict__ bias,
                        const float* __restrict__ x)
{
    extern __shared__ float smem[];
    int row0 = blockIdx.y * 128, col0 = blockIdx.x * 128;
    float acc[2][8][4] = {};
    gemm_tc2<8, false>(g_ao + (size_t)row0 * DD, DD, W + col0, DD, DD, smem, acc);
    EPI_SETUP();
#pragma unroll
    for (int mt = 0; mt < 2; mt++)
#pragma unroll
        for (int nt = 0; nt < 8; nt++) {
            int n = col0 + wn * 64 + nt * 8 + 2 * tig;
            float b0 = bias[n], b1 = bias[n + 1];
#pragma unroll
            for (int half = 0; half < 2; half++) {
                int m = row0 + wm * 32 + mt * 16 + g + half * 8;
                size_t idx = (size_t)m * DD + n;
                float2 xv = *(const float2*)&x[idx];
                float2 v2 = make_float2(xv.x + acc[mt][nt][2 * half] + b0,
                                        xv.y + acc[mt][nt][2 * half + 1] + b1);
                *(float2*)&g_x2[idx] = v2;
            }
        }
}

// expert hidden: w_e * gelu(h2[b] @ w1[e] + b1[e]); skip zero-weight experts
__global__ void expert_hid_tc(const float* __restrict__ w1, const float* __restrict__ b1)
{
    int z = blockIdx.z;
    int e = z >> 3, b = z & 7;
    float wv = g_wgt[b * EE + e];
    if (wv == 0.0f) return;
    extern __shared__ float smem[];
    int row0 = blockIdx.y * 128, col0 = blockIdx.x * 128;
    float acc[2][8][4] = {};
    gemm_tc2<8, false>(g_h2 + ((size_t)b * SS + row0) * DD, DD,
                       w1 + (size_t)e * DD * HID + col0, HID, DD, smem, acc);
    EPI_SETUP();
    float* dst = g_ehid + ((size_t)e * BB + b) * SS * HID;
#pragma unroll
    for (int mt = 0; mt < 2; mt++)
#pragma unroll
        for (int nt = 0; nt < 8; nt++) {
            int n = col0 + wn * 64 + nt * 8 + 2 * tig;
            float b0 = b1[e * HID + n], bx = b1[e * HID + n + 1];
#pragma unroll
            for (int half = 0; half < 2; half++) {
                int m = row0 + wm * 32 + mt * 16 + g + half * 8;
                float2 v2 = make_float2(wv * geluf(acc[mt][nt][2 * half] + b0),
                                        wv * geluf(acc[mt][nt][2 * half + 1] + bx));
                *(float2*)&dst[(size_t)m * HID + n] = v2;
            }
        }
}

// expert out: y[b] = sum_e (hid_scaled[e][b] @ w2[e]) + sum_e w_e*b2[e]
__global__ void expert_out_tc(const float* __restrict__ w2, const float* __restrict__ b2)
{
    extern __shared__ float smem[];
    __shared__ float s_bias[128];
    int b = blockIdx.z;
    int row0 = blockIdx.y * 128, col0 = blockIdx.x * 128;
    float acc[2][8][4] = {};
    for (int e = 0; e < EE; e++) {
        float wv = g_wgt[b * EE + e];
        if (wv == 0.0f) continue;
        gemm_tc2<8, false>(g_ehid + (((size_t)e * BB + b) * SS + row0) * HID, HID,
                           w2 + (size_t)e * HID * DD + col0, DD, HID, smem, acc);
    }
    if (threadIdx.x < 128) {
        float s = 0.0f;
        for (int e = 0; e < EE; e++)
            s += g_wgt[b * EE + e] * b2[e * DD + col0 + threadIdx.x];
        s_bias[threadIdx.x] = s;
    }
    __syncthreads();
    EPI_SETUP();
#pragma unroll
    for (int mt = 0; mt < 2; mt++)
#pragma unroll
        for (int nt = 0; nt < 8; nt++) {
            int nl = wn * 64 + nt * 8 + 2 * tig;
            float b0 = s_bias[nl], b1v = s_bias[nl + 1];
#pragma unroll
            for (int half = 0; half < 2; half++) {
                int m = row0 + wm * 32 + mt * 16 + g + half * 8;
                float2 v2 = make_float2(acc[mt][nt][2 * half] + b0,
                                        acc[mt][nt][2 * half + 1] + b1v);
                *(float2*)&g_y[((size_t)b * SS + m) * DD + col0 + nl] = v2;
            }
        }
}

// shared expert hidden: shid = gelu(h2 @ sh_w1 + sh_b1)
__global__ void shared_hid_tc(const float* __restrict__ W, const float* __restrict__ b1)
{
    extern __shared__ float smem[];
    int row0 = blockIdx.y * 128, col0 = blockIdx.x * 128;
    float acc[2][8][4] = {};
    gemm_tc2<8, false>(g_h2 + (size_t)row0 * DD, DD, W + col0, SHH, DD, smem, acc);
    EPI_SETUP();
#pragma unroll
    for (int mt = 0; mt < 2; mt++)
#pragma unroll
        for (int nt = 0; nt < 8; nt++) {
            int n = col0 + wn * 64 + nt * 8 + 2 * tig;
            float b0 = b1[n], bx = b1[n + 1];
#pragma unroll
            for (int half = 0; half < 2; half++) {
                int m = row0 + wm * 32 + mt * 16 + g + half * 8;
                float2 v2 = make_float2(geluf(acc[mt][nt][2 * half] + b0),
                                        geluf(acc[mt][nt][2 * half + 1] + bx));
                *(float2*)&g_shid[(size_t)m * SHH + n] = v2;
            }
        }
}

// out = x2 + y + shid @ sh_w2 + sh_b2
__global__ void final_tc(const float* __restrict__ W, const float* __restrict__ b2,
                         float* __restrict__ out)
{
    extern __shared__ float smem[];
    int row0 = blockIdx.y * 128, col0 = blockIdx.x * 128;
    float acc[2][8][4] = {};
    gemm_tc2<8, false>(g_shid + (size_t)row0 * SHH, SHH, W + col0, DD, SHH, smem, acc);
    EPI_SETUP();
#pragma unroll
    for (int mt = 0; mt < 2; mt++)
#pragma unroll
        for (int nt = 0; nt < 8; nt++) {
            int n = col0 + wn * 64 + nt * 8 + 2 * tig;
            float b0 = b2[n], bx = b2[n + 1];
#pragma unroll
            for (int half = 0; half < 2; half++) {
                int m = row0 + wm * 32 + mt * 16 + g + half * 8;
                size_t idx = (size_t)m * DD + n;
                float2 xv = *(const float2*)&g_x2[idx];
                float2 yv = *(const float2*)&g_y[idx];
                float2 v2 = make_float2(xv.x + yv.x + acc[mt][nt][2 * half] + b0,
                                        xv.y + yv.y + acc[mt][nt][2 * half + 1] + bx);
                *(float2*)&out[idx] = v2;
            }
        }
}

// ---------------- launch ----------------
extern "C" void kernel_launch(void* const* d_in, const int* in_sizes, int n_in,
                              void* d_out, int out_size)
{
    const float* x         = (const float*)d_in[0];
    const float* ln1_g     = (const float*)d_in[1];
    const float* ln1_b     = (const float*)d_in[2];
    const float* qkv_w     = (const float*)d_in[3];
    const float* proj_w    = (const float*)d_in[4];
    const float* proj_b    = (const float*)d_in[5];
    const float* ln2_g     = (const float*)d_in[6];
    const float* ln2_b     = (const float*)d_in[7];
    const float* router_w1 = (const float*)d_in[8];
    const float* router_b1 = (const float*)d_in[9];
    const float* router_w2 = (const float*)d_in[10];
    const float* router_b2 = (const float*)d_in[11];
    const float* exp_w1    = (const float*)d_in[12];
    const float* exp_b1    = (const float*)d_in[13];
    const float* exp_w2    = (const float*)d_in[14];
    const float* exp_b2    = (const float*)d_in[15];
    const float* sh_w1     = (const float*)d_in[16];
    const float* sh_b1     = (const float*)d_in[17];
    const float* sh_w2     = (const float*)d_in[18];
    const float* sh_b2     = (const float*)d_in[19];
    float* out = (float*)d_out;

    // raise dynamic smem limits (idempotent, host-side, capture-safe)
    cudaFuncSetAttribute(qkv_tc,         cudaFuncAttributeMaxDynamicSharedMemorySize, SMEMB_STD);
    cudaFuncSetAttribute(attn_scores_tc, cudaFuncAttributeMaxDynamicSharedMemorySize, SMEMB_BNK);
    cudaFuncSetAttribute(av_tc,          cudaFuncAttributeMaxDynamicSharedMemorySize, SMEMB_AV);
    cudaFuncSetAttribute(proj_tc,        cudaFuncAttributeMaxDynamicSharedMemorySize, SMEMB_STD);
    cudaFuncSetAttribute(expert_hid_tc,  cudaFuncAttributeMaxDynamicSharedMemorySize, SMEMB_STD);
    cudaFuncSetAttribute(expert_out_tc,  cudaFuncAttributeMaxDynamicSharedMemorySize, SMEMB_STD);
    cudaFuncSetAttribute(shared_hid_tc,  cudaFuncAttributeMaxDynamicSharedMemorySize, SMEMB_STD);
    cudaFuncSetAttribute(final_tc,       cudaFuncAttributeMaxDynamicSharedMemorySize, SMEMB_STD);

    float* h1; cudaGetSymbolAddress((void**)&h1, g_h1);
    float* h2; cudaGetSymbolAddress((void**)&h2, g_h2);
    float* x2; cudaGetSymbolAddress((void**)&x2, g_x2);

    // attention branch
    ln_kernel<<<NTOK, 256>>>(x, ln1_g, ln1_b, h1);
    qkv_tc<<<dim3(18, 32), 256, SMEMB_STD>>>(qkv_w);
    attn_scores_tc<<<dim3(4, 4, BHN), 256, SMEMB_BNK>>>();
    softmax_kernel<<<BHN * SS, 256>>>();
    av_tc<<<dim3(1, 4, BHN), 256, SMEMB_AV>>>();
    proj_tc<<<dim3(6, 32), 256, SMEMB_STD>>>(proj_w, proj_b, x);

    // MoE branch
    ln_kernel<<<NTOK, 256>>>(x2, ln2_g, ln2_b, h2);
    seqmean_kernel<<<dim3(3, BB), 256>>>();
    router_kernel<<<BB, 256>>>(router_w1, router_b1, router_w2, router_b2);
    expert_hid_tc<<<dim3(12, 4, EE * BB), 256, SMEMB_STD>>>(exp_w1, exp_b1);
    expert_out_tc<<<dim3(6, 4, BB), 256, SMEMB_STD>>>(exp_w2, exp_b2);
    shared_hid_tc<<<dim3(24, 32), 256, SMEMB_STD>>>(sh_w1, sh_b1);
    final_tc<<<dim3(6, 32), 256, SMEMB_STD>>>(sh_w2, sh_b2, out);
}

// round 4
// speedup vs baseline: 5.8778x; 1.1704x over previous
#include <cuda_runtime.h>
#include <cstdint>
#include <math.h>

// ---------------- problem constants ----------------
#define BB   8
#define SS   512
#define DD   768
#define HH   12
#define DH   64
#define EE   14
#define KK   4
#define HID  1536
#define SHH  3072
#define NTOK (BB*SS)          // 4096
#define BHN  (BB*HH)          // 96

// ---------------- scratch (device globals; no allocation) ----------------
__device__ float g_h1  [(size_t)NTOK*DD];
__device__ float g_q   [(size_t)BHN*SS*DH];
__device__ float g_k   [(size_t)BHN*SS*DH];
__device__ float g_v   [(size_t)BHN*SS*DH];
__device__ float g_ao  [(size_t)NTOK*DD];
__device__ float g_x2  [(size_t)NTOK*DD];
__device__ float g_h2  [(size_t)NTOK*DD];
__device__ float g_seq [(size_t)BB*DD];
__device__ float g_wgt [(size_t)BB*EE];
__device__ float g_ehid[(size_t)EE*BB*SS*HID];
__device__ float g_shid[(size_t)NTOK*SHH];
__device__ float g_part[8][(size_t)NTOK*DD];   // 0..3 expert-slot partials, 4..7 final split-K

// ---------------- helpers ----------------
__device__ __forceinline__ float geluf(float x) {
    return 0.5f * x * (1.0f + erff(x * 0.70710678118654752f));
}

__device__ __forceinline__ uint32_t f2tf32(float f) {
    uint32_t u;
    asm("cvt.rna.tf32.f32 %0, %1;" : "=r"(u) : "f"(f));
    return u;
}
__device__ __forceinline__ float rnd_tf32(float f) { return __uint_as_float(f2tf32(f)); }

__device__ __forceinline__ void ldsm4(uint32_t &r0, uint32_t &r1, uint32_t &r2, uint32_t &r3,
                                      uint32_t addr) {
    asm volatile("ldmatrix.sync.aligned.m8n8.x4.shared.b16 {%0,%1,%2,%3}, [%4];"
                 : "=r"(r0), "=r"(r1), "=r"(r2), "=r"(r3) : "r"(addr));
}

__device__ __forceinline__ void mma_tf32(float c[4], const uint32_t a[4], const uint32_t b[2]) {
    asm volatile("mma.sync.aligned.m16n8k8.row.col.f32.tf32.tf32.f32 "
                 "{%0,%1,%2,%3}, {%4,%5,%6,%7}, {%8,%9}, {%0,%1,%2,%3};"
                 : "+f"(c[0]), "+f"(c[1]), "+f"(c[2]), "+f"(c[3])
                 : "r"(a[0]), "r"(a[1]), "r"(a[2]), "r"(a[3]), "r"(b[0]), "r"(b[1]));
}

__device__ __forceinline__ void cp16(float* dst_smem, const float* src) {
    uint32_t d = (uint32_t)__cvta_generic_to_shared(dst_smem);
    asm volatile("cp.async.cg.shared.global [%0], [%1], 16;" :: "r"(d), "l"(src));
}

__device__ __forceinline__ float blockReduceSum(float v, float* sh) {
    int tid = threadIdx.x;
    sh[tid] = v; __syncthreads();
    for (int s = 128; s > 0; s >>= 1) {
        if (tid < s) sh[tid] += sh[tid + s];
        __syncthreads();
    }
    float r = sh[0]; __syncthreads();
    return r;
}

// ======================================================================
// tf32 tensor-core GEMM core (cp.async double-buffered, raw-bits tf32).
// Block tile: 128 x (NT*16), BK=32, 256 threads = 8 warps (4m x 2n).
// ======================================================================
template<int NT, bool BNK>
__device__ __forceinline__ void gemm_tc2(const float* __restrict__ A, int lda,
                                         const float* __restrict__ B, int ldb,
                                         int K, float* smem, float acc[2][NT][4])
{
    constexpr int BN  = NT * 16;
    constexpr int LDB = BNK ? 36 : (BN == 128 ? 136 : 72);
    constexpr int ASZ = 128 * 36;
    constexpr int BSZ = BNK ? (BN * 36) : (32 * LDB);

    float* sA0 = smem;
    float* sA1 = smem + ASZ;
    float* sB0 = smem + 2 * ASZ;
    float* sB1 = smem + 2 * ASZ + BSZ;

    const int tid  = threadIdx.x;
    const int lane = tid & 31;
    const int w    = tid >> 5;
    const int wm   = w >> 1;
    const int wn   = w & 1;
    const int lr   = lane & 7;
    const int sub  = lane >> 3;
    const int a_row  = (sub & 1) * 8 + lr;
    const int a_koff = (sub >> 1) * 4;
    const int b_row  = (sub >> 1) * 8 + lr;
    const int b_koff = (sub & 1) * 4;
    const int bk = lane & 3;
    const int bg = lane >> 2;

#define LOAD_A(kt, dst)                                                     \
    {                                                                       \
        _Pragma("unroll")                                                   \
        for (int i = 0; i < 4; i++) {                                       \
            int e = tid + i * 256;                                          \
            int row = e >> 3, v = e & 7;                                    \
            cp16((dst) + row * 36 + v * 4, A + (size_t)row * lda + (kt) + v * 4); \
        }                                                                   \
    }
#define LOAD_B(kt, dst)                                                     \
    {                                                                       \
        if (BNK) {                                                          \
            _Pragma("unroll")                                               \
            for (int i = 0; i < BN / 32; i++) {                             \
                int e = tid + i * 256;                                      \
                int row = e >> 3, v = e & 7;                                \
                cp16((dst) + row * 36 + v * 4, B + (size_t)row * ldb + (kt) + v * 4); \
            }                                                               \
        } else {                                                            \
            _Pragma("unroll")                                               \
            for (int i = 0; i < BN / 32; i++) {                             \
                int e = tid + i * 256;                                      \
                int row = e / (BN / 4), v = e % (BN / 4);                   \
                cp16((dst) + row * LDB + v * 4, B + (size_t)((kt) + row) * ldb + v * 4); \
            }                                                               \
        }                                                                   \
    }

    const int nst = K / 32;
    LOAD_A(0, sA0); LOAD_B(0, sB0);
    asm volatile("cp.async.commit_group;");

    for (int t = 0; t < nst; t++) {
        float* cA = (t & 1) ? sA1 : sA0;
        float* cB = (t & 1) ? sB1 : sB0;
        if (t + 1 < nst) {
            float* nA = (t & 1) ? sA0 : sA1;
            float* nB = (t & 1) ? sB0 : sB1;
            int kt = (t + 1) * 32;
            LOAD_A(kt, nA); LOAD_B(kt, nB);
            asm volatile("cp.async.commit_group;");
            asm volatile("cp.async.wait_group 1;" ::: "memory");
        } else {
            asm volatile("cp.async.wait_group 0;" ::: "memory");
        }
        __syncthreads();

        uint32_t sa0 = (uint32_t)__cvta_generic_to_shared(cA);
        uint32_t sb0 = (uint32_t)__cvta_generic_to_shared(cB);
#pragma unroll
        for (int kk = 0; kk < 4; kk++) {
            int k0 = kk * 8;
            uint32_t a[2][4];
#pragma unroll
            for (int mt = 0; mt < 2; mt++) {
                ldsm4(a[mt][0], a[mt][1], a[mt][2], a[mt][3],
                      sa0 + 4u * ((wm * 32 + mt * 16 + a_row) * 36 + k0 + a_koff));
            }
            uint32_t b[NT][2];
            if (BNK) {
#pragma unroll
                for (int p = 0; p < NT / 2; p++) {
                    uint32_t r0, r1, r2, r3;
                    ldsm4(r0, r1, r2, r3,
                          sb0 + 4u * ((wn * NT * 8 + p * 16 + b_row) * 36 + k0 + b_koff));
                    b[2 * p][0] = r0; b[2 * p][1] = r1;
                    b[2 * p + 1][0] = r2; b[2 * p + 1][1] = r3;
                }
            } else {
                const float* base0 = cB + (k0 + bk) * LDB + wn * NT * 8 + bg;
#pragma unroll
                for (int nt = 0; nt < NT; nt++) {
                    b[nt][0] = __float_as_uint(base0[nt * 8]);
                    b[nt][1] = __float_as_uint(base0[nt * 8 + 4 * LDB]);
                }
            }
#pragma unroll
            for (int mt = 0; mt < 2; mt++)
#pragma unroll
                for (int nt = 0; nt < NT; nt++)
                    mma_tf32(acc[mt][nt], a[mt], b[nt]);
        }
        __syncthreads();
    }
#undef LOAD_A
#undef LOAD_B
}

#define SMEMB_STD  ((2*128*36 + 2*32*136) * 4)   // 71680
#define SMEMB_N4   ((2*128*36 + 2*32*72)  * 4)   // 55296

// ---------------- flash attention (fused scores+softmax+AV) ----------------
#define FQ_STRIDE 68
#define FV_STRIDE 72
#define FP_STRIDE 132
#define SQ_OFF 0
#define SK_OFF (128*FQ_STRIDE)
#define SV_OFF (SK_OFF + 128*FQ_STRIDE)
#define SP_OFF (SV_OFF + 128*FV_STRIDE)
#define FLASH_SMEM ((SP_OFF + 128*FP_STRIDE) * 4)   // 174080 bytes

__global__ void __launch_bounds__(256, 1) flash_tc()
{
    extern __shared__ float smem[];
    float* sQ = smem + SQ_OFF;
    float* sK = smem + SK_OFF;
    float* sV = smem + SV_OFF;
    float* sP = smem + SP_OFF;

    const int bh = blockIdx.y;
    const int q0 = blockIdx.x * 128;
    const float* Qg = g_q + ((size_t)bh * SS + q0) * DH;
    const float* Kg = g_k + (size_t)bh * SS * DH;
    const float* Vg = g_v + (size_t)bh * SS * DH;

    const int tid = threadIdx.x, lane = tid & 31, w = tid >> 5;
    const int lr = lane & 7, sub = lane >> 3;
    const int a_row = (sub & 1) * 8 + lr, a_koff = (sub >> 1) * 4;
    const int b_row = (sub >> 1) * 8 + lr, b_koff = (sub & 1) * 4;
    const int bk = lane & 3;
    const int g = lane >> 2, tig = lane & 3;   // also bg = g

#define FCOPY(dst, src, stride)                                             \
    { _Pragma("unroll")                                                     \
      for (int i = 0; i < 8; i++) {                                         \
          int e = tid + i * 256; int r = e >> 4, v = e & 15;                \
          cp16((dst) + r * (stride) + v * 4, (src) + (size_t)r * 64 + v * 4); } }

    FCOPY(sQ, Qg, FQ_STRIDE);
    FCOPY(sK, Kg, FQ_STRIDE);
    asm volatile("cp.async.commit_group;");
    FCOPY(sV, Vg, FV_STRIDE);
    asm volatile("cp.async.commit_group;");

    float acc_o[8][4] = {};
    float mrun[2] = {-1e30f, -1e30f};
    float lrun[2] = {0.0f, 0.0f};

    const uint32_t sQa = (uint32_t)__cvta_generic_to_shared(sQ);
    const uint32_t sKa = (uint32_t)__cvta_generic_to_shared(sK);
    const uint32_t sPa = (uint32_t)__cvta_generic_to_shared(sP);

    for (int st = 0; st < 4; st++) {
        // wait for K[st] (V[st] may still fly)
        asm volatile("cp.async.wait_group 1;" ::: "memory");
        __syncthreads();

        // ---- S = Q @ K^T  (this warp: rows w*16..w*16+15, all 128 cols) ----
        float s[16][4] = {};
#pragma unroll
        for (int k0 = 0; k0 < 64; k0 += 8) {
            uint32_t a[4];
            ldsm4(a[0], a[1], a[2], a[3],
                  sQa + 4u * ((w * 16 + a_row) * FQ_STRIDE + k0 + a_koff));
#pragma unroll
            for (int p = 0; p < 8; p++) {
                uint32_t b0[2], b1[2];
                ldsm4(b0[0], b0[1], b1[0], b1[1],
                      sKa + 4u * ((p * 16 + b_row) * FQ_STRIDE + k0 + b_koff));
                mma_tf32(s[2 * p], a, b0);
                mma_tf32(s[2 * p + 1], a, b1);
            }
        }

        // ---- online softmax ----
        float tmax[2] = {-1e30f, -1e30f};
#pragma unroll
        for (int nt = 0; nt < 16; nt++) {
            tmax[0] = fmaxf(tmax[0], fmaxf(s[nt][0], s[nt][1]));
            tmax[1] = fmaxf(tmax[1], fmaxf(s[nt][2], s[nt][3]));
        }
#pragma unroll
        for (int o = 1; o < 4; o <<= 1) {
            tmax[0] = fmaxf(tmax[0], __shfl_xor_sync(0xffffffffu, tmax[0], o));
            tmax[1] = fmaxf(tmax[1], __shfl_xor_sync(0xffffffffu, tmax[1], o));
        }
        float mnew[2], corr[2], rsum[2] = {0.0f, 0.0f};
#pragma unroll
        for (int h = 0; h < 2; h++) {
            mnew[h] = fmaxf(mrun[h], tmax[h] * 0.125f);
            corr[h] = __expf(mrun[h] - mnew[h]);
            mrun[h] = mnew[h];
        }
        const int prow0 = w * 16 + g;
#pragma unroll
        for (int nt = 0; nt < 16; nt++) {
            float p0 = __expf(s[nt][0] * 0.125f - mnew[0]);
            float p1 = __expf(s[nt][1] * 0.125f - mnew[0]);
            float p2 = __expf(s[nt][2] * 0.125f - mnew[1]);
            float p3 = __expf(s[nt][3] * 0.125f - mnew[1]);
            rsum[0] += p0 + p1; rsum[1] += p2 + p3;
            int col = nt * 8 + 2 * tig;
            *(float2*)(sP + prow0 * FP_STRIDE + col) =
                make_float2(rnd_tf32(p0), rnd_tf32(p1));
            *(float2*)(sP + (prow0 + 8) * FP_STRIDE + col) =
                make_float2(rnd_tf32(p2), rnd_tf32(p3));
        }
#pragma unroll
        for (int o = 1; o < 4; o <<= 1) {
            rsum[0] += __shfl_xor_sync(0xffffffffu, rsum[0], o);
            rsum[1] += __shfl_xor_sync(0xffffffffu, rsum[1], o);
        }
        lrun[0] = lrun[0] * corr[0] + rsum[0];
        lrun[1] = lrun[1] * corr[1] + rsum[1];
#pragma unroll
        for (int nt = 0; nt < 8; nt++) {
            acc_o[nt][0] *= corr[0]; acc_o[nt][1] *= corr[0];
            acc_o[nt][2] *= corr[1]; acc_o[nt][3] *= corr[1];
        }
        __syncwarp();

        // wait V[st]; block barrier also releases sK for overwrite
        asm volatile("cp.async.wait_group 0;" ::: "memory");
        __syncthreads();
        if (st < 3) {
            const float* Kn = Kg + (size_t)(st + 1) * 128 * 64;
            FCOPY(sK, Kn, FQ_STRIDE);
            asm volatile("cp.async.commit_group;");
        }

        // ---- O += P @ V ----
#pragma unroll
        for (int k0 = 0; k0 < 128; k0 += 8) {
            uint32_t a[4];
            ldsm4(a[0], a[1], a[2], a[3],
                  sPa + 4u * ((w * 16 + a_row) * FP_STRIDE + k0 + a_koff));
            const float* vb = sV + (k0 + bk) * FV_STRIDE + g;
#pragma unroll
            for (int nt = 0; nt < 8; nt++) {
                uint32_t b[2];
                b[0] = __float_as_uint(vb[nt * 8]);
                b[1] = __float_as_uint(vb[nt * 8 + 4 * FV_STRIDE]);
                mma_tf32(acc_o[nt], a, b);
            }
        }
        __syncthreads();
        if (st < 3) {
            const float* Vn = Vg + (size_t)(st + 1) * 128 * 64;
            FCOPY(sV, Vn, FV_STRIDE);
            asm volatile("cp.async.commit_group;");
        }
    }

    // ---- epilogue: O /= l, scatter heads ----
    const int b = bh / HH, hh = bh - b * HH;
    const float inv0 = 1.0f / lrun[0], inv1 = 1.0f / lrun[1];
    const int m0 = q0 + w * 16 + g;
#pragma unroll
    for (int nt = 0; nt < 8; nt++) {
        int d = nt * 8 + 2 * tig;
        *(float2*)&g_ao[((size_t)b * SS + m0) * DD + hh * DH + d] =
            make_float2(rnd_tf32(acc_o[nt][0] * inv0), rnd_tf32(acc_o[nt][1] * inv0));
        *(float2*)&g_ao[((size_t)b * SS + m0 + 8) * DD + hh * DH + d] =
            make_float2(rnd_tf32(acc_o[nt][2] * inv1), rnd_tf32(acc_o[nt][3] * inv1));
    }
#undef FCOPY
}

// ---------------- elementwise kernels ----------------

__global__ void ln_kernel(const float* __restrict__ in, const float* __restrict__ g,
                          const float* __restrict__ b, float* __restrict__ out, int rnd)
{
    __shared__ float red[256];
    size_t row = blockIdx.x;
    const float* xr = in + row * DD;
    int tid = threadIdx.x;
    float x0 = xr[tid], x1 = xr[tid + 256], x2 = xr[tid + 512];
    float total = blockReduceSum(x0 + x1 + x2, red);
    float mean = total * (1.0f / DD);
    float d0 = x0 - mean, d1 = x1 - mean, d2 = x2 - mean;
    float var = blockReduceSum(d0 * d0 + d1 * d1 + d2 * d2, red) * (1.0f / DD);
    float rstd = rsqrtf(var + 1e-5f);
    float r0 = d0 * rstd * g[tid]       + b[tid];
    float r1 = d1 * rstd * g[tid + 256] + b[tid + 256];
    float r2 = d2 * rstd * g[tid + 512] + b[tid + 512];
    if (rnd) { r0 = rnd_tf32(r0); r1 = rnd_tf32(r1); r2 = rnd_tf32(r2); }
    out[row * DD + tid]       = r0;
    out[row * DD + tid + 256] = r1;
    out[row * DD + tid + 512] = r2;
}

__global__ void seqmean_kernel()
{
    int b = blockIdx.y;
    int d = blockIdx.x * 256 + threadIdx.x;
    const float* p = g_h2 + (size_t)b * SS * DD + d;
    float s = 0.0f;
    for (int i = 0; i < SS; i++) s += p[(size_t)i * DD];
    g_seq[b * DD + d] = s * (1.0f / SS);
}

__global__ void router_kernel(const float* __restrict__ w1, const float* __restrict__ b1,
                              const float* __restrict__ w2, const float* __restrict__ b2)
{
    __shared__ float s_in[DD];
    __shared__ float s_hid[DD];
    __shared__ float s_logits[EE];
    int b = blockIdx.x;
    int tid = threadIdx.x;
    for (int i = tid; i < DD; i += 256) s_in[i] = g_seq[b * DD + i];
    __syncthreads();
    for (int j = tid; j < DD; j += 256) {
        float a = b1[j];
        for (int d = 0; d < DD; d++) a = fmaf(s_in[d], w1[(size_t)d * DD + j], a);
        s_hid[j] = geluf(a);
    }
    __syncthreads();
    if (tid < EE) {
        float a = b2[tid];
        for (int d = 0; d < DD; d++) a = fmaf(s_hid[d], w2[(size_t)d * EE + tid], a);
        s_logits[tid] = a;
    }
    __syncthreads();
    if (tid == 0) {
        float p[EE];
        float mx = -1e30f;
        for (int e = 0; e < EE; e++) mx = fmaxf(mx, s_logits[e]);
        float sum = 0.0f;
        for (int e = 0; e < EE; e++) { p[e] = expf(s_logits[e] - mx); sum += p[e]; }
        float inv = 1.0f / sum;
        for (int e = 0; e < EE; e++) p[e] *= inv;
        int   idx[KK];
        float val[KK];
        bool used[EE] = {};
        for (int k = 0; k < KK; k++) {
            int best = -1; float bv = -1e30f;
            for (int e = 0; e < EE; e++)
                if (!used[e] && p[e] > bv) { bv = p[e]; best = e; }
            used[best] = true; idx[k] = best; val[k] = bv;
        }
        float m2 = val[0];
        float s2 = 0.0f, tw[KK];
        for (int k = 0; k < KK; k++) { tw[k] = expf(val[k] - m2); s2 += tw[k]; }
        float inv2 = 1.0f / s2;
        for (int e = 0; e < EE; e++) g_wgt[b * EE + e] = 0.0f;
        for (int k = 0; k < KK; k++) g_wgt[b * EE + idx[k]] = tw[k] * inv2;
    }
}

// ---------------- tensor-core GEMM kernels ----------------

#define EPI_SETUP()                                             \
    const int tid = threadIdx.x;                                \
    const int lane = tid & 31, w = tid >> 5;                    \
    const int wm = w >> 1, wn = w & 1;                          \
    const int g = lane >> 2, tig = lane & 3;

// QKV: [4096,768] @ [768,2304] -> scatter q/k/v (tf32-rounded)
__global__ void qkv_tc(const float* __restrict__ W)
{
    extern __shared__ float smem[];
    int row0 = blockIdx.y * 128, col0 = blockIdx.x * 128;
    float acc[2][8][4] = {};
    gemm_tc2<8, false>(g_h1 + (size_t)row0 * DD, DD, W + col0, 3 * DD, DD, smem, acc);
    EPI_SETUP();
#pragma unroll
    for (int mt = 0; mt < 2; mt++)
#pragma unroll
        for (int nt = 0; nt < 8; nt++) {
            int n = col0 + wn * 64 + nt * 8 + 2 * tig;
            int which = n / DD;
            int rem = n - which * DD;
            int h = rem >> 6, d = rem & 63;
            float* dst = (which == 0) ? g_q : ((which == 1) ? g_k : g_v);
#pragma unroll
            for (int half = 0; half < 2; half++) {
                int m = row0 + wm * 32 + mt * 16 + g + half * 8;
                int b = m >> 9, s = m & 511;
                float2 v2 = make_float2(rnd_tf32(acc[mt][nt][2 * half]),
                                        rnd_tf32(acc[mt][nt][2 * half + 1]));
                *(float2*)&dst[(((size_t)b * HH + h) * SS + s) * DH + d] = v2;
            }
        }
}

// proj: x2 = x + ao @ proj_w + proj_b   (128x64 tiles, 384 blocks)
__global__ void proj_tc(const float* __restrict__ W, const float* __restrict__ bias,
                        const float* __restrict__ x)
{
    extern __shared__ float smem[];
    int row0 = blockIdx.y * 128, col0 = blockIdx.x * 64;
    float acc[2][4][4] = {};
    gemm_tc2<4, false>(g_ao + (size_t)row0 * DD, DD, W + col0, DD, DD, smem, acc);
    EPI_SETUP();
#pragma unroll
    for (int mt = 0; mt < 2; mt++)
#pragma unroll
        for (int nt = 0; nt < 4; nt++) {
            int n = col0 + wn * 32 + nt * 8 + 2 * tig;
            float b0 = bias[n], b1 = bias[n + 1];
#pragma unroll
            for (int half = 0; half < 2; half++) {
                int m = row0 + wm * 32 + mt * 16 + g + half * 8;
                size_t idx = (size_t)m * DD + n;
                float2 xv = *(const float2*)&x[idx];
                float2 v2 = make_float2(xv.x + acc[mt][nt][2 * half] + b0,
                                        xv.y + acc[mt][nt][2 * half + 1] + b1);
                *(float2*)&g_x2[idx] = v2;
            }
        }
}

// expert hidden: w_e * gelu(h2[b] @ w1[e] + b1[e]) (tf32-rounded)
__global__ void expert_hid_tc(const float* __restrict__ w1, const float* __restrict__ b1)
{
    int z = blockIdx.z;
    int e = z >> 3, b = z & 7;
    float wv = g_wgt[b * EE + e];
    if (wv == 0.0f) return;
    extern __shared__ float smem[];
    int row0 = blockIdx.y * 128, col0 = blockIdx.x * 128;
    float acc[2][8][4] = {};
    gemm_tc2<8, false>(g_h2 + ((size_t)b * SS + row0) * DD, DD,
                       w1 + (size_t)e * DD * HID + col0, HID, DD, smem, acc);
    EPI_SETUP();
    float* dst = g_ehid + ((size_t)e * BB + b) * SS * HID;
#pragma unroll
    for (int mt = 0; mt < 2; mt++)
#pragma unroll
        for (int nt = 0; nt < 8; nt++) {
            int n = col0 + wn * 64 + nt * 8 + 2 * tig;
            float b0 = b1[e * HID + n], bx = b1[e * HID + n + 1];
#pragma unroll
            for (int half = 0; half < 2; half++) {
                int m = row0 + wm * 32 + mt * 16 + g + half * 8;
                float2 v2 = make_float2(rnd_tf32(wv * geluf(acc[mt][nt][2 * half] + b0)),
                                        rnd_tf32(wv * geluf(acc[mt][nt][2 * half + 1] + bx)));
                *(float2*)&dst[(size_t)m * HID + n] = v2;
            }
        }
}

// expert out, slot-parallel: one block per (b, top-k slot); writes g_part[slot]
__global__ void expert_out_slot_tc(const float* __restrict__ w2, const float* __restrict__ b2)
{
    extern __shared__ float smem[];
    int b = blockIdx.z >> 2, slot = blockIdx.z & 3;
    // slot-th active expert in index order (deterministic; exactly 4 active)
    int e = 0; float wv = 0.0f;
    {
        int cnt = -1;
        for (int j = 0; j < EE; j++) {
            float t = g_wgt[b * EE + j];
            if (t != 0.0f) { cnt++; if (cnt == slot) { e = j; wv = t; break; } }
        }
    }
    int row0 = blockIdx.y * 128, col0 = blockIdx.x * 128;
    float acc[2][8][4] = {};
    gemm_tc2<8, false>(g_ehid + (((size_t)e * BB + b) * SS + row0) * HID, HID,
                       w2 + (size_t)e * HID * DD + col0, DD, HID, smem, acc);
    EPI_SETUP();
    float* dst = g_part[slot];
#pragma unroll
    for (int mt = 0; mt < 2; mt++)
#pragma unroll
        for (int nt = 0; nt < 8; nt++) {
            int n = col0 + wn * 64 + nt * 8 + 2 * tig;
            float b0 = wv * b2[e * DD + n], b1v = wv * b2[e * DD + n + 1];
#pragma unroll
            for (int half = 0; half < 2; half++) {
                int m = row0 + wm * 32 + mt * 16 + g + half * 8;
                float2 v2 = make_float2(acc[mt][nt][2 * half] + b0,
                                        acc[mt][nt][2 * half + 1] + b1v);
                *(float2*)&dst[((size_t)b * SS + m) * DD + n] = v2;
            }
        }
}

// shared expert hidden: shid = gelu(h2 @ sh_w1 + sh_b1) (tf32-rounded)
__global__ void shared_hid_tc(const float* __restrict__ W, const float* __restrict__ b1)
{
    extern __shared__ float smem[];
    int row0 = blockIdx.y * 128, col0 = blockIdx.x * 128;
    float acc[2][8][4] = {};
    gemm_tc2<8, false>(g_h2 + (size_t)row0 * DD, DD, W + col0, SHH, DD, smem, acc);
    EPI_SETUP();
#pragma unroll
    for (int mt = 0; mt < 2; mt++)
#pragma unroll
        for (int nt = 0; nt < 8; nt++) {
            int n = col0 + wn * 64 + nt * 8 + 2 * tig;
            float b0 = b1[n], bx = b1[n + 1];
#pragma unroll
            for (int half = 0; half < 2; half++) {
                int m = row0 + wm * 32 + mt * 16 + g + half * 8;
                float2 v2 = make_float2(rnd_tf32(geluf(acc[mt][nt][2 * half] + b0)),
                                        rnd_tf32(geluf(acc[mt][nt][2 * half + 1] + bx)));
                *(float2*)&g_shid[(size_t)m * SHH + n] = v2;
            }
        }
}

// final GEMM split-K: chunk c computes shid[:, c*768:(c+1)*768] @ W[c*768:...,:]
__global__ void final_split_tc(const float* __restrict__ W)
{
    extern __shared__ float smem[];
    int c = blockIdx.z;
    int row0 = blockIdx.y * 128, col0 = blockIdx.x * 128;
    float acc[2][8][4] = {};
    gemm_tc2<8, false>(g_shid + (size_t)row0 * SHH + c * 768, SHH,
                       W + (size_t)(c * 768) * DD + col0, DD, 768, smem, acc);
    EPI_SETUP();
    float* dst = g_part[4 + c];
#pragma unroll
    for (int mt = 0; mt < 2; mt++)
#pragma unroll
        for (int nt = 0; nt < 8; nt++) {
            int n = col0 + wn * 64 + nt * 8 + 2 * tig;
#pragma unroll
            for (int half = 0; half < 2; half++) {
                int m = row0 + wm * 32 + mt * 16 + g + half * 8;
                float2 v2 = make_float2(acc[mt][nt][2 * half], acc[mt][nt][2 * half + 1]);
                *(float2*)&dst[(size_t)m * DD + n] = v2;
            }
        }
}

// out = x2 + sum(expert slot partials) + sum(final splits) + sh_b2
__global__ void final_sum_kernel(const float* __restrict__ b2, float* __restrict__ out)
{
    int i = blockIdx.x * 256 + threadIdx.x;          // float4 index
    int n = (i % (DD / 4)) * 4;
    float4 r = *(const float4*)(g_x2 + (size_t)i * 4);
#pragma unroll
    for (int j = 0; j < 8; j++) {
        float4 p = *(const float4*)(g_part[j] + (size_t)i * 4);
        r.x += p.x; r.y += p.y; r.z += p.z; r.w += p.w;
    }
    float4 bb = *(const float4*)(b2 + n);
    r.x += bb.x; r.y += bb.y; r.z += bb.z; r.w += bb.w;
    *(float4*)(out + (size_t)i * 4) = r;
}

// ---------------- launch ----------------
extern "C" void kernel_launch(void* const* d_in, const int* in_sizes, int n_in,
                              void* d_out, int out_size)
{
    const float* x         = (const float*)d_in[0];
    const float* ln1_g     = (const float*)d_in[1];
    const float* ln1_b     = (const float*)d_in[2];
    const float* qkv_w     = (const float*)d_in[3];
    const float* proj_w    = (const float*)d_in[4];
    const float* proj_b    = (const float*)d_in[5];
    const float* ln2_g     = (const float*)d_in[6];
    const float* ln2_b     = (const float*)d_in[7];
    const float* router_w1 = (const float*)d_in[8];
    const float* router_b1 = (const float*)d_in[9];
    const float* router_w2 = (const float*)d_in[10];
    const float* router_b2 = (const float*)d_in[11];
    const float* exp_w1    = (const float*)d_in[12];
    const float* exp_b1    = (const float*)d_in[13];
    const float* exp_w2    = (const float*)d_in[14];
    const float* exp_b2    = (const float*)d_in[15];
    const float* sh_w1     = (const float*)d_in[16];
    const float* sh_b1     = (const float*)d_in[17];
    const float* sh_w2     = (const float*)d_in[18];
    const float* sh_b2     = (const float*)d_in[19];
    float* out = (float*)d_out;

    cudaFuncSetAttribute(qkv_tc,             cudaFuncAttributeMaxDynamicSharedMemorySize, SMEMB_STD);
    cudaFuncSetAttribute(proj_tc,            cudaFuncAttributeMaxDynamicSharedMemorySize, SMEMB_N4);
    cudaFuncSetAttribute(expert_hid_tc,      cudaFuncAttributeMaxDynamicSharedMemorySize, SMEMB_STD);
    cudaFuncSetAttribute(expert_out_slot_tc, cudaFuncAttributeMaxDynamicSharedMemorySize, SMEMB_STD);
    cudaFuncSetAttribute(shared_hid_tc,      cudaFuncAttributeMaxDynamicSharedMemorySize, SMEMB_STD);
    cudaFuncSetAttribute(final_split_tc,     cudaFuncAttributeMaxDynamicSharedMemorySize, SMEMB_STD);
    cudaFuncSetAttribute(flash_tc,           cudaFuncAttributeMaxDynamicSharedMemorySize, FLASH_SMEM);

    float* h1; cudaGetSymbolAddress((void**)&h1, g_h1);
    float* h2; cudaGetSymbolAddress((void**)&h2, g_h2);
    float* x2; cudaGetSymbolAddress((void**)&x2, g_x2);

    // attention branch
    ln_kernel<<<NTOK, 256>>>(x, ln1_g, ln1_b, h1, 1);
    qkv_tc<<<dim3(18, 32), 256, SMEMB_STD>>>(qkv_w);
    flash_tc<<<dim3(4, BHN), 256, FLASH_SMEM>>>();
    proj_tc<<<dim3(12, 32), 256, SMEMB_N4>>>(proj_w, proj_b, x);

    // MoE branch
    ln_kernel<<<NTOK, 256>>>(x2, ln2_g, ln2_b, h2, 0);
    seqmean_kernel<<<dim3(3, BB), 256>>>();
    router_kernel<<<BB, 256>>>(router_w1, router_b1, router_w2, router_b2);
    expert_hid_tc<<<dim3(12, 4, EE * BB), 256, SMEMB_STD>>>(exp_w1, exp_b1);
    expert_out_slot_tc<<<dim3(6, 4, BB * KK), 256, SMEMB_STD>>>(exp_w2, exp_b2);
    shared_hid_tc<<<dim3(24, 32), 256, SMEMB_STD>>>(sh_w1, sh_b1);
    final_split_tc<<<dim3(6, 32, 4), 256, SMEMB_STD>>>(sh_w2);
    final_sum_kernel<<<NTOK * DD / 4 / 256, 256>>>(sh_b2, out);
}

// round 5
// speedup vs baseline: 8.5244x; 1.4503x over previous
#include <cuda_runtime.h>
#include <cuda_fp16.h>
#include <cstdint>
#include <math.h>

// ---------------- problem constants ----------------
#define BB   8
#define SS   512
#define DD   768
#define HH   12
#define DH   64
#define EE   14
#define KK   4
#define HID  1536
#define SHH  3072
#define NTOK (BB*SS)          // 4096
#define BHN  (BB*HH)          // 96

// ---------------- scratch (device globals; no allocation) ----------------
__device__ __align__(128) __half g_h1h [(size_t)NTOK*DD];
__device__ __align__(128) __half g_qh  [(size_t)BHN*SS*DH];
__device__ __align__(128) __half g_kh  [(size_t)BHN*SS*DH];
__device__ __align__(128) __half g_vh  [(size_t)BHN*SS*DH];
__device__ __align__(128) __half g_aoh [(size_t)NTOK*DD];
__device__ __align__(128) float  g_x2  [(size_t)NTOK*DD];
__device__ __align__(128) float  g_h2f [(size_t)NTOK*DD];
__device__ __align__(128) __half g_h2h [(size_t)NTOK*DD];
__device__ __align__(128) float  g_seq [(size_t)BB*DD];
__device__ __align__(128) float  g_wgt [(size_t)BB*EE];
__device__ int g_eact[EE];
__device__ __align__(128) __half g_ehidh[(size_t)EE*BB*SS*HID];
__device__ __align__(128) __half g_shidh[(size_t)NTOK*SHH];
__device__ __align__(128) float  g_part[8][(size_t)NTOK*DD];
// fp16 weight mirrors
__device__ __align__(128) __half g_qkvw_h [(size_t)DD*3*DD];
__device__ __align__(128) __half g_projw_h[(size_t)DD*DD];
__device__ __align__(128) __half g_shw1_h [(size_t)DD*SHH];
__device__ __align__(128) __half g_shw2_h [(size_t)SHH*DD];
__device__ __align__(128) __half g_expw1_h[(size_t)EE*DD*HID];
__device__ __align__(128) __half g_expw2_h[(size_t)EE*HID*DD];

// ---------------- helpers ----------------
__device__ __forceinline__ float geluf(float x) {
    return 0.5f * x * (1.0f + erff(x * 0.70710678118654752f));
}

__device__ __forceinline__ void ldsm4(uint32_t &r0, uint32_t &r1, uint32_t &r2, uint32_t &r3,
                                      uint32_t addr) {
    asm volatile("ldmatrix.sync.aligned.m8n8.x4.shared.b16 {%0,%1,%2,%3}, [%4];"
                 : "=r"(r0), "=r"(r1), "=r"(r2), "=r"(r3) : "r"(addr));
}
__device__ __forceinline__ void ldsm4t(uint32_t &r0, uint32_t &r1, uint32_t &r2, uint32_t &r3,
                                       uint32_t addr) {
    asm volatile("ldmatrix.sync.aligned.m8n8.x4.trans.shared.b16 {%0,%1,%2,%3}, [%4];"
                 : "=r"(r0), "=r"(r1), "=r"(r2), "=r"(r3) : "r"(addr));
}

__device__ __forceinline__ void mma_f16(float c[4], const uint32_t a[4], const uint32_t b[2]) {
    asm volatile("mma.sync.aligned.m16n8k16.row.col.f32.f16.f16.f32 "
                 "{%0,%1,%2,%3}, {%4,%5,%6,%7}, {%8,%9}, {%0,%1,%2,%3};"
                 : "+f"(c[0]), "+f"(c[1]), "+f"(c[2]), "+f"(c[3])
                 : "r"(a[0]), "r"(a[1]), "r"(a[2]), "r"(a[3]), "r"(b[0]), "r"(b[1]));
}

__device__ __forceinline__ void cp16h(__half* dst_smem, const __half* src) {
    uint32_t d = (uint32_t)__cvta_generic_to_shared(dst_smem);
    asm volatile("cp.async.cg.shared.global [%0], [%1], 16;" :: "r"(d), "l"(src));
}

__device__ __forceinline__ uint32_t packh2(float a, float b) {
    __half2 h = __floats2half2_rn(a, b);
    return *(uint32_t*)&h;
}

__device__ __forceinline__ float blockReduceSum(float v, float* sh) {
    int tid = threadIdx.x;
    sh[tid] = v; __syncthreads();
    for (int s = 128; s > 0; s >>= 1) {
        if (tid < s) sh[tid] += sh[tid + s];
        __syncthreads();
    }
    float r = sh[0]; __syncthreads();
    return r;
}

// ======================================================================
// fp16 tensor-core GEMM core (cp.async double-buffered, m16n8k16).
// Block tile: 128 x (NT*16), BK=32, 256 threads = 8 warps (4m x 2n).
// A: global [M][K] fp16 row-major (pre-offset), smem [m][k] ld=40.
// B: global [K][N] fp16 row-major (pre-offset), smem [k][n] ld=BN+8,
//    fragments via ldmatrix.trans.
// ======================================================================
template<int NT>
__device__ __forceinline__ void gemm_h(const __half* __restrict__ A, int lda,
                                       const __half* __restrict__ B, int ldb,
                                       int K, __half* smem, float acc[2][NT][4])
{
    constexpr int BN  = NT * 16;
    constexpr int LDA = 40;
    constexpr int LDB = BN + 8;
    constexpr int ASZ = 128 * LDA;
    constexpr int BSZ = 32 * LDB;
    constexpr int CPR = BN / 8;            // 16B chunks per B row

    __half* sA0 = smem;
    __half* sA1 = smem + ASZ;
    __half* sB0 = smem + 2 * ASZ;
    __half* sB1 = smem + 2 * ASZ + BSZ;

    const int tid  = threadIdx.x;
    const int lane = tid & 31;
    const int w    = tid >> 5;
    const int wm   = w >> 1;
    const int wn   = w & 1;
    const int l16  = lane & 15;
    const int lh   = lane >> 4;

#define LOAD_A(kt, dst)                                                       \
    { _Pragma("unroll")                                                       \
      for (int i = 0; i < 2; i++) {                                           \
          int e = tid + i * 256; int row = e >> 2, v = e & 3;                 \
          cp16h((dst) + row * LDA + v * 8, A + (size_t)row * lda + (kt) + v * 8); } }
#define LOAD_B(kt, dst)                                                       \
    { _Pragma("unroll")                                                       \
      for (int i = 0; i < (32 * CPR) / 256; i++) {                            \
          int e = tid + i * 256; int row = e / CPR, v = e % CPR;              \
          cp16h((dst) + row * LDB + v * 8, B + (size_t)((kt) + row) * ldb + v * 8); } }

    const int nst = K / 32;
    LOAD_A(0, sA0); LOAD_B(0, sB0);
    asm volatile("cp.async.commit_group;");

    for (int t = 0; t < nst; t++) {
        __half* cA = (t & 1) ? sA1 : sA0;
        __half* cB = (t & 1) ? sB1 : sB0;
        if (t + 1 < nst) {
            __half* nA = (t & 1) ? sA0 : sA1;
            __half* nB = (t & 1) ? sB0 : sB1;
            int kt = (t + 1) * 32;
            LOAD_A(kt, nA); LOAD_B(kt, nB);
            asm volatile("cp.async.commit_group;");
            asm volatile("cp.async.wait_group 1;" ::: "memory");
        } else {
            asm volatile("cp.async.wait_group 0;" ::: "memory");
        }
        __syncthreads();

        uint32_t sAa = (uint32_t)__cvta_generic_to_shared(cA);
        uint32_t sBa = (uint32_t)__cvta_generic_to_shared(cB);
#pragma unroll
        for (int kk = 0; kk < 2; kk++) {
            int k0 = kk * 16;
            uint32_t a[2][4];
#pragma unroll
            for (int mt = 0; mt < 2; mt++)
                ldsm4(a[mt][0], a[mt][1], a[mt][2], a[mt][3],
                      sAa + 2u * ((wm * 32 + mt * 16 + l16) * LDA + k0 + lh * 8));
            uint32_t b[NT][2];
#pragma unroll
            for (int p = 0; p < NT / 2; p++) {
                uint32_t r0, r1, r2, r3;
                ldsm4t(r0, r1, r2, r3,
                       sBa + 2u * ((k0 + l16) * LDB + wn * NT * 8 + p * 16 + lh * 8));
                b[2 * p][0] = r0; b[2 * p][1] = r1;
                b[2 * p + 1][0] = r2; b[2 * p + 1][1] = r3;
            }
#pragma unroll
            for (int mt = 0; mt < 2; mt++)
#pragma unroll
                for (int nt = 0; nt < NT; nt++)
                    mma_f16(acc[mt][nt], a[mt], b[nt]);
        }
        __syncthreads();
    }
#undef LOAD_A
#undef LOAD_B
}

#define SMEMB_STD  ((2*128*40 + 2*32*136) * 2)   // 37888 B (NT=8)
#define SMEMB_N4   ((2*128*40 + 2*32*72)  * 2)   // 29696 B (NT=4)

// ---------------- flash attention (fp16, P stays in registers) ----------------
#define FLDA 72
#define FLASH_SMEM (3 * 128 * FLDA * 2)          // 55296 B

__global__ void __launch_bounds__(256, 1) flash_tc()
{
    extern __shared__ __half hsm[];
    __half* sQ = hsm;
    __half* sK = hsm + 128 * FLDA;
    __half* sV = hsm + 2 * 128 * FLDA;

    const int bh = blockIdx.y;
    const int q0 = blockIdx.x * 128;
    const __half* Qg = g_qh + ((size_t)bh * SS + q0) * DH;
    const __half* Kg = g_kh + (size_t)bh * SS * DH;
    const __half* Vg = g_vh + (size_t)bh * SS * DH;

    const int tid = threadIdx.x, lane = tid & 31, w = tid >> 5;
    const int l16 = lane & 15, lh = lane >> 4;
    const int g = lane >> 2, tig = lane & 3;

#define FCOPY(dst, src)                                                       \
    { _Pragma("unroll")                                                       \
      for (int i = 0; i < 4; i++) {                                           \
          int e = tid + i * 256; int r = e >> 3, v = e & 7;                   \
          cp16h((dst) + r * FLDA + v * 8, (src) + (size_t)r * 64 + v * 8); } }

    FCOPY(sQ, Qg);
    FCOPY(sK, Kg);
    asm volatile("cp.async.commit_group;");
    FCOPY(sV, Vg);
    asm volatile("cp.async.commit_group;");

    float acc_o[8][4] = {};
    float mrun[2] = {-1e30f, -1e30f};
    float lrun[2] = {0.0f, 0.0f};

    const uint32_t sQa = (uint32_t)__cvta_generic_to_shared(sQ);
    const uint32_t sKa = (uint32_t)__cvta_generic_to_shared(sK);
    const uint32_t sVa = (uint32_t)__cvta_generic_to_shared(sV);

    for (int st = 0; st < 4; st++) {
        asm volatile("cp.async.wait_group 1;" ::: "memory");
        __syncthreads();

        // ---- S = Q @ K^T ----
        float s[16][4] = {};
#pragma unroll
        for (int kk = 0; kk < 4; kk++) {
            int k0 = kk * 16;
            uint32_t a[4];
            ldsm4(a[0], a[1], a[2], a[3],
                  sQa + 2u * ((w * 16 + l16) * FLDA + k0 + lh * 8));
#pragma unroll
            for (int p = 0; p < 8; p++) {
                uint32_t r0, r1, r2, r3;
                ldsm4(r0, r1, r2, r3,
                      sKa + 2u * ((p * 16 + l16) * FLDA + k0 + lh * 8));
                uint32_t b0[2] = {r0, r2}, b1[2] = {r1, r3};
                mma_f16(s[2 * p], a, b0);
                mma_f16(s[2 * p + 1], a, b1);
            }
        }

        // ---- online softmax; pack P to half2 in registers ----
        float tmax[2] = {-1e30f, -1e30f};
#pragma unroll
        for (int nt = 0; nt < 16; nt++) {
            tmax[0] = fmaxf(tmax[0], fmaxf(s[nt][0], s[nt][1]));
            tmax[1] = fmaxf(tmax[1], fmaxf(s[nt][2], s[nt][3]));
        }
#pragma unroll
        for (int o = 1; o < 4; o <<= 1) {
            tmax[0] = fmaxf(tmax[0], __shfl_xor_sync(0xffffffffu, tmax[0], o));
            tmax[1] = fmaxf(tmax[1], __shfl_xor_sync(0xffffffffu, tmax[1], o));
        }
        float mnew[2], corr[2], rsum[2] = {0.0f, 0.0f};
#pragma unroll
        for (int h = 0; h < 2; h++) {
            mnew[h] = fmaxf(mrun[h], tmax[h] * 0.125f);
            corr[h] = __expf(mrun[h] - mnew[h]);
            mrun[h] = mnew[h];
        }
        uint32_t ph[16][2];
#pragma unroll
        for (int nt = 0; nt < 16; nt++) {
            float p0 = __expf(s[nt][0] * 0.125f - mnew[0]);
            float p1 = __expf(s[nt][1] * 0.125f - mnew[0]);
            float p2 = __expf(s[nt][2] * 0.125f - mnew[1]);
            float p3 = __expf(s[nt][3] * 0.125f - mnew[1]);
            rsum[0] += p0 + p1; rsum[1] += p2 + p3;
            ph[nt][0] = packh2(p0, p1);
            ph[nt][1] = packh2(p2, p3);
        }
#pragma unroll
        for (int o = 1; o < 4; o <<= 1) {
            rsum[0] += __shfl_xor_sync(0xffffffffu, rsum[0], o);
            rsum[1] += __shfl_xor_sync(0xffffffffu, rsum[1], o);
        }
        lrun[0] = lrun[0] * corr[0] + rsum[0];
        lrun[1] = lrun[1] * corr[1] + rsum[1];
#pragma unroll
        for (int nt = 0; nt < 8; nt++) {
            acc_o[nt][0] *= corr[0]; acc_o[nt][1] *= corr[0];
            acc_o[nt][2] *= corr[1]; acc_o[nt][3] *= corr[1];
        }

        asm volatile("cp.async.wait_group 0;" ::: "memory");
        __syncthreads();
        if (st < 3) {
            FCOPY(sK, Kg + (size_t)(st + 1) * 128 * 64);
            asm volatile("cp.async.commit_group;");
        }

        // ---- O += P @ V  (A frags come straight from ph registers) ----
#pragma unroll
        for (int j = 0; j < 8; j++) {
            int k0 = j * 16;
            uint32_t a[4] = {ph[2 * j][0], ph[2 * j][1], ph[2 * j + 1][0], ph[2 * j + 1][1]};
#pragma unroll
            for (int p = 0; p < 4; p++) {
                uint32_t r0, r1, r2, r3;
                ldsm4t(r0, r1, r2, r3,
                       sVa + 2u * ((k0 + l16) * FLDA + p * 16 + lh * 8));
                uint32_t b0[2] = {r0, r1}, b1[2] = {r2, r3};
                mma_f16(acc_o[2 * p], a, b0);
                mma_f16(acc_o[2 * p + 1], a, b1);
            }
        }
        __syncthreads();
        if (st < 3) {
            FCOPY(sV, Vg + (size_t)(st + 1) * 128 * 64);
            asm volatile("cp.async.commit_group;");
        }
    }

    // ---- epilogue: O /= l, scatter heads (fp16) ----
    const int b = bh / HH, hh = bh - b * HH;
    const float inv0 = 1.0f / lrun[0], inv1 = 1.0f / lrun[1];
    const int m0 = q0 + w * 16 + g;
#pragma unroll
    for (int nt = 0; nt < 8; nt++) {
        int d = nt * 8 + 2 * tig;
        *(__half2*)&g_aoh[((size_t)b * SS + m0) * DD + hh * DH + d] =
            __floats2half2_rn(acc_o[nt][0] * inv0, acc_o[nt][1] * inv0);
        *(__half2*)&g_aoh[((size_t)b * SS + m0 + 8) * DD + hh * DH + d] =
            __floats2half2_rn(acc_o[nt][2] * inv1, acc_o[nt][3] * inv1);
    }
#undef FCOPY
}

// ---------------- conversion kernels ----------------
__global__ void f2h_kernel(const float* __restrict__ in, __half* __restrict__ out, int n8)
{
    int i = blockIdx.x * 256 + threadIdx.x;
    if (i >= n8) return;
    float4 a = ((const float4*)in)[2 * i];
    float4 b = ((const float4*)in)[2 * i + 1];
    uint4 u;
    u.x = packh2(a.x, a.y); u.y = packh2(a.z, a.w);
    u.z = packh2(b.x, b.y); u.w = packh2(b.z, b.w);
    ((uint4*)out)[i] = u;
}

// convert active experts' w1+w2 (gated by g_eact)
__global__ void expconv_kernel(const float* __restrict__ w1, const float* __restrict__ w2)
{
    int e = blockIdx.y;
    if (!g_eact[e]) return;
    int i = blockIdx.x * 256 + threadIdx.x;   // 0 .. 2*147456-1
    const int n8 = DD * HID / 8;              // 147456 per matrix
    const float* src; __half* dst; int j;
    if (i < n8) { src = w1 + (size_t)e * DD * HID; dst = g_expw1_h + (size_t)e * DD * HID; j = i; }
    else        { src = w2 + (size_t)e * HID * DD; dst = g_expw2_h + (size_t)e * HID * DD; j = i - n8; }
    float4 a = ((const float4*)src)[2 * j];
    float4 b = ((const float4*)src)[2 * j + 1];
    uint4 u;
    u.x = packh2(a.x, a.y); u.y = packh2(a.z, a.w);
    u.z = packh2(b.x, b.y); u.w = packh2(b.z, b.w);
    ((uint4*)dst)[j] = u;
}

__global__ void eact_init_kernel()
{
    if (threadIdx.x < EE) g_eact[threadIdx.x] = 0;
}

// ---------------- elementwise kernels ----------------

// LayerNorm: always writes fp16 outh; optionally fp32 outf
__global__ void ln_kernel(const float* __restrict__ in, const float* __restrict__ g,
                          const float* __restrict__ b, __half* __restrict__ outh,
                          float* __restrict__ outf)
{
    __shared__ float red[256];
    size_t row = blockIdx.x;
    const float* xr = in + row * DD;
    int tid = threadIdx.x;
    float x0 = xr[tid], x1 = xr[tid + 256], x2 = xr[tid + 512];
    float total = blockReduceSum(x0 + x1 + x2, red);
    float mean = total * (1.0f / DD);
    float d0 = x0 - mean, d1 = x1 - mean, d2 = x2 - mean;
    float var = blockReduceSum(d0 * d0 + d1 * d1 + d2 * d2, red) * (1.0f / DD);
    float rstd = rsqrtf(var + 1e-5f);
    float r0 = d0 * rstd * g[tid]       + b[tid];
    float r1 = d1 * rstd * g[tid + 256] + b[tid + 256];
    float r2 = d2 * rstd * g[tid + 512] + b[tid + 512];
    outh[row * DD + tid]       = __float2half_rn(r0);
    outh[row * DD + tid + 256] = __float2half_rn(r1);
    outh[row * DD + tid + 512] = __float2half_rn(r2);
    if (outf) {
        outf[row * DD + tid]       = r0;
        outf[row * DD + tid + 256] = r1;
        outf[row * DD + tid + 512] = r2;
    }
}

__global__ void seqmean_kernel()
{
    int b = blockIdx.y;
    int d = blockIdx.x * 256 + threadIdx.x;
    const float* p = g_h2f + (size_t)b * SS * DD + d;
    float s = 0.0f;
    for (int i = 0; i < SS; i++) s += p[(size_t)i * DD];
    g_seq[b * DD + d] = s * (1.0f / SS);
}

__global__ void router_kernel(const float* __restrict__ w1, const float* __restrict__ b1,
                              const float* __restrict__ w2, const float* __restrict__ b2)
{
    __shared__ float s_in[DD];
    __shared__ float s_hid[DD];
    __shared__ float s_logits[EE];
    int b = blockIdx.x;
    int tid = threadIdx.x;
    for (int i = tid; i < DD; i += 256) s_in[i] = g_seq[b * DD + i];
    __syncthreads();
    for (int j = tid; j < DD; j += 256) {
        float a = b1[j];
        for (int d = 0; d < DD; d++) a = fmaf(s_in[d], w1[(size_t)d * DD + j], a);
        s_hid[j] = geluf(a);
    }
    __syncthreads();
    if (tid < EE) {
        float a = b2[tid];
        for (int d = 0; d < DD; d++) a = fmaf(s_hid[d], w2[(size_t)d * EE + tid], a);
        s_logits[tid] = a;
    }
    __syncthreads();
    if (tid == 0) {
        float p[EE];
        float mx = -1e30f;
        for (int e = 0; e < EE; e++) mx = fmaxf(mx, s_logits[e]);
        float sum = 0.0f;
        for (int e = 0; e < EE; e++) { p[e] = expf(s_logits[e] - mx); sum += p[e]; }
        float inv = 1.0f / sum;
        for (int e = 0; e < EE; e++) p[e] *= inv;
        int   idx[KK];
        float val[KK];
        bool used[EE] = {};
        for (int k = 0; k < KK; k++) {
            int best = -1; float bv = -1e30f;
            for (int e = 0; e < EE; e++)
                if (!used[e] && p[e] > bv) { bv = p[e]; best = e; }
            used[best] = true; idx[k] = best; val[k] = bv;
        }
        float m2 = val[0];
        float s2 = 0.0f, tw[KK];
        for (int k = 0; k < KK; k++) { tw[k] = expf(val[k] - m2); s2 += tw[k]; }
        float inv2 = 1.0f / s2;
        for (int e = 0; e < EE; e++) g_wgt[b * EE + e] = 0.0f;
        for (int k = 0; k < KK; k++) {
            g_wgt[b * EE + idx[k]] = tw[k] * inv2;
            g_eact[idx[k]] = 1;
        }
    }
}

// ---------------- tensor-core GEMM kernels ----------------

#define EPI_SETUP()                                             \
    const int tid = threadIdx.x;                                \
    const int lane = tid & 31, w = tid >> 5;                    \
    const int wm = w >> 1, wn = w & 1;                          \
    const int g = lane >> 2, tig = lane & 3;

// QKV: h1h[4096,768] @ qkvw_h[768,2304] -> q/k/v fp16
__global__ void qkv_tc()
{
    extern __shared__ __half smem[];
    int row0 = blockIdx.y * 128, col0 = blockIdx.x * 128;
    float acc[2][8][4] = {};
    gemm_h<8>(g_h1h + (size_t)row0 * DD, DD, g_qkvw_h + col0, 3 * DD, DD, smem, acc);
    EPI_SETUP();
#pragma unroll
    for (int mt = 0; mt < 2; mt++)
#pragma unroll
        for (int nt = 0; nt < 8; nt++) {
            int n = col0 + wn * 64 + nt * 8 + 2 * tig;
            int which = n / DD;
            int rem = n - which * DD;
            int h = rem >> 6, d = rem & 63;
            __half* dst = (which == 0) ? g_qh : ((which == 1) ? g_kh : g_vh);
#pragma unroll
            for (int half_ = 0; half_ < 2; half_++) {
                int m = row0 + wm * 32 + mt * 16 + g + half_ * 8;
                int b = m >> 9, s = m & 511;
                *(__half2*)&dst[(((size_t)b * HH + h) * SS + s) * DH + d] =
                    __floats2half2_rn(acc[mt][nt][2 * half_], acc[mt][nt][2 * half_ + 1]);
            }
        }
}

// proj: x2 = x + aoh @ projw_h + proj_b   (128x64 tiles)
__global__ void proj_tc(const float* __restrict__ bias, const float* __restrict__ x)
{
    extern __shared__ __half smem[];
    int row0 = blockIdx.y * 128, col0 = blockIdx.x * 64;
    float acc[2][4][4] = {};
    gemm_h<4>(g_aoh + (size_t)row0 * DD, DD, g_projw_h + col0, DD, DD, smem, acc);
    EPI_SETUP();
#pragma unroll
    for (int mt = 0; mt < 2; mt++)
#pragma unroll
        for (int nt = 0; nt < 4; nt++) {
            int n = col0 + wn * 32 + nt * 8 + 2 * tig;
            float b0 = bias[n], b1 = bias[n + 1];
#pragma unroll
            for (int half_ = 0; half_ < 2; half_++) {
                int m = row0 + wm * 32 + mt * 16 + g + half_ * 8;
                size_t idx = (size_t)m * DD + n;
                float2 xv = *(const float2*)&x[idx];
                *(float2*)&g_x2[idx] =
                    make_float2(xv.x + acc[mt][nt][2 * half_] + b0,
                                xv.y + acc[mt][nt][2 * half_ + 1] + b1);
            }
        }
}

// expert hidden: ehid = w_e * gelu(h2h[b] @ w1_h[e] + b1[e])   (fp16 out)
__global__ void expert_hid_tc(const float* __restrict__ b1)
{
    int z = blockIdx.z;
    int e = z >> 3, b = z & 7;
    float wv = g_wgt[b * EE + e];
    if (wv == 0.0f) return;
    extern __shared__ __half smem[];
    int row0 = blockIdx.y * 128, col0 = blockIdx.x * 128;
    float acc[2][8][4] = {};
    gemm_h<8>(g_h2h + ((size_t)b * SS + row0) * DD, DD,
              g_expw1_h + (size_t)e * DD * HID + col0, HID, DD, smem, acc);
    EPI_SETUP();
    __half* dst = g_ehidh + ((size_t)e * BB + b) * SS * HID;
#pragma unroll
    for (int mt = 0; mt < 2; mt++)
#pragma unroll
        for (int nt = 0; nt < 8; nt++) {
            int n = col0 + wn * 64 + nt * 8 + 2 * tig;
            float b0 = b1[e * HID + n], bx = b1[e * HID + n + 1];
#pragma unroll
            for (int half_ = 0; half_ < 2; half_++) {
                int m = row0 + wm * 32 + mt * 16 + g + half_ * 8;
                *(__half2*)&dst[(size_t)m * HID + n] =
                    __floats2half2_rn(wv * geluf(acc[mt][nt][2 * half_] + b0),
                                      wv * geluf(acc[mt][nt][2 * half_ + 1] + bx));
            }
        }
}

// expert out, slot-parallel: one block set per (b, top-k slot) -> g_part[slot]
__global__ void expert_out_slot_tc(const float* __restrict__ b2)
{
    extern __shared__ __half smem[];
    int b = blockIdx.z >> 2, slot = blockIdx.z & 3;
    int e = 0; float wv = 0.0f;
    {
        int cnt = -1;
        for (int j = 0; j < EE; j++) {
            float t = g_wgt[b * EE + j];
            if (t != 0.0f) { cnt++; if (cnt == slot) { e = j; wv = t; break; } }
        }
    }
    int row0 = blockIdx.y * 128, col0 = blockIdx.x * 128;
    float acc[2][8][4] = {};
    gemm_h<8>(g_ehidh + (((size_t)e * BB + b) * SS + row0) * HID, HID,
              g_expw2_h + (size_t)e * HID * DD + col0, DD, HID, smem, acc);
    EPI_SETUP();
    float* dst = g_part[slot];
#pragma unroll
    for (int mt = 0; mt < 2; mt++)
#pragma unroll
        for (int nt = 0; nt < 8; nt++) {
            int n = col0 + wn * 64 + nt * 8 + 2 * tig;
            float b0 = wv * b2[e * DD + n], b1v = wv * b2[e * DD + n + 1];
#pragma unroll
            for (int half_ = 0; half_ < 2; half_++) {
                int m = row0 + wm * 32 + mt * 16 + g + half_ * 8;
                *(float2*)&dst[((size_t)b * SS + m) * DD + n] =
                    make_float2(acc[mt][nt][2 * half_] + b0,
                                acc[mt][nt][2 * half_ + 1] + b1v);
            }
        }
}

// shared expert hidden: shid = gelu(h2h @ shw1_h + sh_b1) (fp16 out)
__global__ void shared_hid_tc(const float* __restrict__ b1)
{
    extern __shared__ __half smem[];
    int row0 = blockIdx.y * 128, col0 = blockIdx.x * 128;
    float acc[2][8][4] = {};
    gemm_h<8>(g_h2h + (size_t)row0 * DD, DD, g_shw1_h + col0, SHH, DD, smem, acc);
    EPI_SETUP();
#pragma unroll
    for (int mt = 0; mt < 2; mt++)
#pragma unroll
        for (int nt = 0; nt < 8; nt++) {
            int n = col0 + wn * 64 + nt * 8 + 2 * tig;
            float b0 = b1[n], bx = b1[n + 1];
#pragma unroll
            for (int half_ = 0; half_ < 2; half_++) {
                int m = row0 + wm * 32 + mt * 16 + g + half_ * 8;
                *(__half2*)&g_shidh[(size_t)m * SHH + n] =
                    __floats2half2_rn(geluf(acc[mt][nt][2 * half_] + b0),
                                      geluf(acc[mt][nt][2 * half_ + 1] + bx));
            }
        }
}

// final GEMM split-K: chunk c -> g_part[4+c]
__global__ void final_split_tc()
{
    extern __shared__ __half smem[];
    int c = blockIdx.z;
    int row0 = blockIdx.y * 128, col0 = blockIdx.x * 128;
    float acc[2][8][4] = {};
    gemm_h<8>(g_shidh + (size_t)row0 * SHH + c * 768, SHH,
              g_shw2_h + (size_t)(c * 768) * DD + col0, DD, 768, smem, acc);
    EPI_SETUP();
    float* dst = g_part[4 + c];
#pragma unroll
    for (int mt = 0; mt < 2; mt++)
#pragma unroll
        for (int nt = 0; nt < 8; nt++) {
            int n = col0 + wn * 64 + nt * 8 + 2 * tig;
#pragma unroll
            for (int half_ = 0; half_ < 2; half_++) {
                int m = row0 + wm * 32 + mt * 16 + g + half_ * 8;
                *(float2*)&dst[(size_t)m * DD + n] =
                    make_float2(acc[mt][nt][2 * half_], acc[mt][nt][2 * half_ + 1]);
            }
        }
}

// out = x2 + sum(expert slot partials) + sum(final splits) + sh_b2
__global__ void final_sum_kernel(const float* __restrict__ b2, float* __restrict__ out)
{
    int i = blockIdx.x * 256 + threadIdx.x;
    int n = (i % (DD / 4)) * 4;
    float4 r = *(const float4*)(g_x2 + (size_t)i * 4);
#pragma unroll
    for (int j = 0; j < 8; j++) {
        float4 p = *(const float4*)(g_part[j] + (size_t)i * 4);
        r.x += p.x; r.y += p.y; r.z += p.z; r.w += p.w;
    }
    float4 bb = *(const float4*)(b2 + n);
    r.x += bb.x; r.y += bb.y; r.z += bb.z; r.w += bb.w;
    *(float4*)(out + (size_t)i * 4) = r;
}

// ---------------- launch ----------------
extern "C" void kernel_launch(void* const* d_in, const int* in_sizes, int n_in,
                              void* d_out, int out_size)
{
    const float* x         = (const float*)d_in[0];
    const float* ln1_g     = (const float*)d_in[1];
    const float* ln1_b     = (const float*)d_in[2];
    const float* qkv_w     = (const float*)d_in[3];
    const float* proj_w    = (const float*)d_in[4];
    const float* proj_b    = (const float*)d_in[5];
    const float* ln2_g     = (const float*)d_in[6];
    const float* ln2_b     = (const float*)d_in[7];
    const float* router_w1 = (const float*)d_in[8];
    const float* router_b1 = (const float*)d_in[9];
    const float* router_w2 = (const float*)d_in[10];
    const float* router_b2 = (const float*)d_in[11];
    const float* exp_w1    = (const float*)d_in[12];
    const float* exp_b1    = (const float*)d_in[13];
    const float* exp_w2    = (const float*)d_in[14];
    const float* exp_b2    = (const float*)d_in[15];
    const float* sh_w1     = (const float*)d_in[16];
    const float* sh_b1     = (const float*)d_in[17];
    const float* sh_w2     = (const float*)d_in[18];
    const float* sh_b2     = (const float*)d_in[19];
    float* out = (float*)d_out;

    cudaFuncSetAttribute(qkv_tc,             cudaFuncAttributeMaxDynamicSharedMemorySize, SMEMB_STD);
    cudaFuncSetAttribute(proj_tc,            cudaFuncAttributeMaxDynamicSharedMemorySize, SMEMB_N4);
    cudaFuncSetAttribute(expert_hid_tc,      cudaFuncAttributeMaxDynamicSharedMemorySize, SMEMB_STD);
    cudaFuncSetAttribute(expert_out_slot_tc, cudaFuncAttributeMaxDynamicSharedMemorySize, SMEMB_STD);
    cudaFuncSetAttribute(shared_hid_tc,      cudaFuncAttributeMaxDynamicSharedMemorySize, SMEMB_STD);
    cudaFuncSetAttribute(final_split_tc,     cudaFuncAttributeMaxDynamicSharedMemorySize, SMEMB_STD);
    cudaFuncSetAttribute(flash_tc,           cudaFuncAttributeMaxDynamicSharedMemorySize, FLASH_SMEM);

    __half* wq; cudaGetSymbolAddress((void**)&wq, g_qkvw_h);
    __half* wp; cudaGetSymbolAddress((void**)&wp, g_projw_h);
    __half* w1; cudaGetSymbolAddress((void**)&w1, g_shw1_h);
    __half* w2; cudaGetSymbolAddress((void**)&w2, g_shw2_h);
    __half* h1h; cudaGetSymbolAddress((void**)&h1h, g_h1h);
    __half* h2h; cudaGetSymbolAddress((void**)&h2h, g_h2h);
    float*  h2f; cudaGetSymbolAddress((void**)&h2f, g_h2f);
    float*  x2;  cudaGetSymbolAddress((void**)&x2,  g_x2);

    // weight conversions (attn + shared; experts gated after router)
    f2h_kernel<<<(DD*3*DD/8 + 255)/256, 256>>>(qkv_w, wq, DD*3*DD/8);
    f2h_kernel<<<(DD*DD/8   + 255)/256, 256>>>(proj_w, wp, DD*DD/8);
    f2h_kernel<<<(DD*SHH/8  + 255)/256, 256>>>(sh_w1, w1, DD*SHH/8);
    f2h_kernel<<<(SHH*DD/8  + 255)/256, 256>>>(sh_w2, w2, SHH*DD/8);

    // attention branch
    ln_kernel<<<NTOK, 256>>>(x, ln1_g, ln1_b, h1h, nullptr);
    qkv_tc<<<dim3(18, 32), 256, SMEMB_STD>>>();
    flash_tc<<<dim3(4, BHN), 256, FLASH_SMEM>>>();
    proj_tc<<<dim3(12, 32), 256, SMEMB_N4>>>(proj_b, x);

    // MoE branch
    ln_kernel<<<NTOK, 256>>>(x2, ln2_g, ln2_b, h2h, h2f);
    seqmean_kernel<<<dim3(3, BB), 256>>>();
    eact_init_kernel<<<1, 32>>>();
    router_kernel<<<BB, 256>>>(router_w1, router_b1, router_w2, router_b2);
    expconv_kernel<<<dim3(2*DD*HID/8/256, EE), 256>>>(exp_w1, exp_w2);
    expert_hid_tc<<<dim3(12, 4, EE * BB), 256, SMEMB_STD>>>(exp_b1);
    expert_out_slot_tc<<<dim3(6, 4, BB * KK), 256, SMEMB_STD>>>(exp_b2);
    shared_hid_tc<<<dim3(24, 32), 256, SMEMB_STD>>>(sh_b1);
    final_split_tc<<<dim3(6, 32, 4), 256, SMEMB_STD>>>();
    final_sum_kernel<<<NTOK * DD / 4 / 256, 256>>>(sh_b2, out);
}

// round 7
// speedup vs baseline: 8.6168x; 1.0108x over previous
#include <cuda_runtime.h>
#include <cuda_fp16.h>
#include <cstdint>
#include <math.h>

// ---------------- problem constants ----------------
#define BB   8
#define SS   512
#define DD   768
#define HH   12
#define DH   64
#define EE   14
#define KK   4
#define HID  1536
#define SHH  3072
#define NTOK (BB*SS)          // 4096
#define BHN  (BB*HH)          // 96

// ---------------- scratch (device globals; no allocation) ----------------
__device__ __align__(128) __half g_h1h [(size_t)NTOK*DD];
__device__ __align__(128) __half g_qh  [(size_t)BHN*SS*DH];
__device__ __align__(128) __half g_kh  [(size_t)BHN*SS*DH];
__device__ __align__(128) __half g_vh  [(size_t)BHN*SS*DH];
__device__ __align__(128) __half g_aoh [(size_t)NTOK*DD];
__device__ __align__(128) float  g_x2  [(size_t)NTOK*DD];
__device__ __align__(128) float  g_h2f [(size_t)NTOK*DD];
__device__ __align__(128) __half g_h2h [(size_t)NTOK*DD];
__device__ __align__(128) float  g_seq [(size_t)BB*DD];
__device__ __align__(128) float  g_wgt [(size_t)BB*EE];
__device__ int g_eact[EE];
__device__ __align__(128) __half g_ehidh[(size_t)EE*BB*SS*HID];
__device__ __align__(128) __half g_shidh[(size_t)NTOK*SHH];
__device__ __align__(128) float  g_part[8][(size_t)NTOK*DD];
// fp16 weight mirrors, [K][N] row-major
__device__ __align__(128) __half g_qkvw_h [(size_t)DD*3*DD];
__device__ __align__(128) __half g_projw_h[(size_t)DD*DD];
__device__ __align__(128) __half g_shw1_h [(size_t)DD*SHH];
__device__ __align__(128) __half g_shw2_h [(size_t)SHH*DD];
__device__ __align__(128) __half g_expw1_h[(size_t)EE*DD*HID];
__device__ __align__(128) __half g_expw2_h[(size_t)EE*HID*DD];

// ---------------- helpers ----------------
__device__ __forceinline__ float geluf(float x) {
    return 0.5f * x * (1.0f + erff(x * 0.70710678118654752f));
}
__device__ __forceinline__ uint32_t packh2(float a, float b) {
    __half2 h = __floats2half2_rn(a, b);
    return *(uint32_t*)&h;
}
__device__ __forceinline__ void cp16h(__half* dst_smem, const __half* src) {
    uint32_t d = (uint32_t)__cvta_generic_to_shared(dst_smem);
    asm volatile("cp.async.cg.shared.global [%0], [%1], 16;" :: "r"(d), "l"(src));
}
__device__ __forceinline__ void ldsm4(uint32_t &r0, uint32_t &r1, uint32_t &r2, uint32_t &r3,
                                      uint32_t addr) {
    asm volatile("ldmatrix.sync.aligned.m8n8.x4.shared.b16 {%0,%1,%2,%3}, [%4];"
                 : "=r"(r0), "=r"(r1), "=r"(r2), "=r"(r3) : "r"(addr));
}
__device__ __forceinline__ void ldsm4t(uint32_t &r0, uint32_t &r1, uint32_t &r2, uint32_t &r3,
                                       uint32_t addr) {
    asm volatile("ldmatrix.sync.aligned.m8n8.x4.trans.shared.b16 {%0,%1,%2,%3}, [%4];"
                 : "=r"(r0), "=r"(r1), "=r"(r2), "=r"(r3) : "r"(addr));
}
__device__ __forceinline__ void mma_f16(float c[4], const uint32_t a[4], const uint32_t b[2]) {
    asm volatile("mma.sync.aligned.m16n8k16.row.col.f32.f16.f16.f32 "
                 "{%0,%1,%2,%3}, {%4,%5,%6,%7}, {%8,%9}, {%0,%1,%2,%3};"
                 : "+f"(c[0]), "+f"(c[1]), "+f"(c[2]), "+f"(c[3])
                 : "r"(a[0]), "r"(a[1]), "r"(a[2]), "r"(a[3]), "r"(b[0]), "r"(b[1]));
}

__device__ __forceinline__ float blockReduceSum(float v, float* sh) {
    int tid = threadIdx.x;
    sh[tid] = v; __syncthreads();
    for (int s = 128; s > 0; s >>= 1) {
        if (tid < s) sh[tid] += sh[tid + s];
        __syncthreads();
    }
    float r = sh[0]; __syncthreads();
    return r;
}

// ======================================================================
// fp16 GEMM core v3: 128 threads / 4 warps, warp tile 64x64, CTA 128x128,
// BK=32, 3-stage cp.async, ONE barrier per k-tile.
// A: [M][K] fp16 row-major (pre-offset), smem [m][k] ld=40.
// B: [K][N] fp16 row-major (pre-offset), smem [k][n] ld=136, ldmatrix.trans.
// ======================================================================
#define G2_LDA 40
#define G2_LDB 136
#define G2_ASZ (128*G2_LDA)               // halves
#define G2_BSZ (32*G2_LDB)
#define G2_STG (G2_ASZ + G2_BSZ)          // 9472 halves = 18944 B
#define SMEMB_G2 (3 * G2_STG * 2)         // 56832 B

__device__ __forceinline__ void gemm2(const __half* __restrict__ A, int lda,
                                      const __half* __restrict__ B, int ldb,
                                      int K, __half* smem, float acc[4][8][4])
{
    const int tid  = threadIdx.x;         // 128
    const int lane = tid & 31;
    const int w    = tid >> 5;
    const int wm   = w >> 1;
    const int wn   = w & 1;
    const int l16  = lane & 15;
    const int lh   = lane >> 4;

#define G2_LOAD(kt, stg)                                                     \
    { __half* bA = smem + (stg) * G2_STG;                                    \
      __half* bBp = bA + G2_ASZ;                                             \
      _Pragma("unroll")                                                      \
      for (int i = 0; i < 4; i++) {                                          \
          int e = tid + i * 128; int row = e >> 2, v = e & 3;                \
          cp16h(bA + row * G2_LDA + v * 8, A + (size_t)row * lda + (kt) + v * 8); } \
      _Pragma("unroll")                                                      \
      for (int i = 0; i < 4; i++) {                                          \
          int e = tid + i * 128; int row = e >> 4, v = e & 15;               \
          cp16h(bBp + row * G2_LDB + v * 8, B + (size_t)((kt) + row) * ldb + v * 8); } }

    const int nst = K / 32;
    G2_LOAD(0, 0);
    asm volatile("cp.async.commit_group;");
    G2_LOAD(32, 1);
    asm volatile("cp.async.commit_group;");

    int stg = 0;
    for (int t = 0; t < nst; t++) {
        if (t + 1 < nst) asm volatile("cp.async.wait_group 1;" ::: "memory");
        else             asm volatile("cp.async.wait_group 0;" ::: "memory");
        __syncthreads();
        if (t + 2 < nst) {
            int ns = stg + 2; if (ns >= 3) ns -= 3;
            G2_LOAD((t + 2) * 32, ns);
            asm volatile("cp.async.commit_group;");
        }
        __half* cA = smem + stg * G2_STG;
        uint32_t aB = (uint32_t)__cvta_generic_to_shared(cA);
        uint32_t bBa = (uint32_t)__cvta_generic_to_shared(cA + G2_ASZ);
#pragma unroll
        for (int kk = 0; kk < 2; kk++) {
            int k0 = kk * 16;
            uint32_t a[4][4];
#pragma unroll
            for (int mt = 0; mt < 4; mt++)
                ldsm4(a[mt][0], a[mt][1], a[mt][2], a[mt][3],
                      aB + 2u * ((wm * 64 + mt * 16 + l16) * G2_LDA + k0 + lh * 8));
            uint32_t b[8][2];
#pragma unroll
            for (int p = 0; p < 4; p++) {
                uint32_t r0, r1, r2, r3;
                ldsm4t(r0, r1, r2, r3,
                       bBa + 2u * ((k0 + l16) * G2_LDB + wn * 64 + p * 16 + lh * 8));
                b[2 * p][0] = r0; b[2 * p][1] = r1;
                b[2 * p + 1][0] = r2; b[2 * p + 1][1] = r3;
            }
#pragma unroll
            for (int mt = 0; mt < 4; mt++)
#pragma unroll
                for (int nt = 0; nt < 8; nt++)
                    mma_f16(acc[mt][nt], a[mt], b[nt]);
        }
        if (++stg == 3) stg = 0;
    }
#undef G2_LOAD
}

// epilogue index setup for gemm2 kernels
#define EPI2_SETUP()                                            \
    const int tid = threadIdx.x;                                \
    const int lane = tid & 31, w = tid >> 5;                    \
    const int wm = w >> 1, wn = w & 1;                          \
    const int g = lane >> 2, tig = lane & 3;

// ---------------- gemm2 kernels (128 threads each) ----------------

// QKV: h1h[4096,768] @ qkvw[768,2304] -> scatter q/k/v fp16
__global__ void __launch_bounds__(128) qkv_g2()
{
    extern __shared__ __half smem[];
    int row0 = blockIdx.y * 128, col0 = blockIdx.x * 128;
    float acc[4][8][4] = {};
    gemm2(g_h1h + (size_t)row0 * DD, DD, g_qkvw_h + col0, 3 * DD, DD, smem, acc);
    EPI2_SETUP();
#pragma unroll
    for (int mt = 0; mt < 4; mt++)
#pragma unroll
        for (int nt = 0; nt < 8; nt++) {
            int n = col0 + wn * 64 + nt * 8 + 2 * tig;
            int which = n / DD;
            int rem = n - which * DD;
            int h = rem >> 6, d = rem & 63;
            __half* dst = (which == 0) ? g_qh : ((which == 1) ? g_kh : g_vh);
#pragma unroll
            for (int hf = 0; hf < 2; hf++) {
                int m = row0 + wm * 64 + mt * 16 + g + hf * 8;
                int b = m >> 9, s = m & 511;
                *(__half2*)&dst[(((size_t)b * HH + h) * SS + s) * DH + d] =
                    __floats2half2_rn(acc[mt][nt][2 * hf], acc[mt][nt][2 * hf + 1]);
            }
        }
}

// proj: x2 = x + aoh @ projw + proj_b
__global__ void __launch_bounds__(128) proj_g2(const float* __restrict__ bias,
                                               const float* __restrict__ x)
{
    extern __shared__ __half smem[];
    int row0 = blockIdx.y * 128, col0 = blockIdx.x * 128;
    float acc[4][8][4] = {};
    gemm2(g_aoh + (size_t)row0 * DD, DD, g_projw_h + col0, DD, DD, smem, acc);
    EPI2_SETUP();
#pragma unroll
    for (int mt = 0; mt < 4; mt++)
#pragma unroll
        for (int nt = 0; nt < 8; nt++) {
            int n = col0 + wn * 64 + nt * 8 + 2 * tig;
            float b0 = bias[n], b1 = bias[n + 1];
#pragma unroll
            for (int hf = 0; hf < 2; hf++) {
                int m = row0 + wm * 64 + mt * 16 + g + hf * 8;
                size_t idx = (size_t)m * DD + n;
                float2 xv = *(const float2*)&x[idx];
                *(float2*)&g_x2[idx] =
                    make_float2(xv.x + acc[mt][nt][2 * hf] + b0,
                                xv.y + acc[mt][nt][2 * hf + 1] + b1);
            }
        }
}

// expert hidden: ehid = w_e * gelu(h2h[b] @ w1[e] + b1[e]) (fp16 out)
__global__ void __launch_bounds__(128) expert_hid_g2(const float* __restrict__ b1)
{
    int z = blockIdx.z;
    int e = z >> 3, b = z & 7;
    float wv = g_wgt[b * EE + e];
    if (wv == 0.0f) return;
    extern __shared__ __half smem[];
    int row0 = blockIdx.y * 128, col0 = blockIdx.x * 128;
    float acc[4][8][4] = {};
    gemm2(g_h2h + ((size_t)b * SS + row0) * DD, DD,
          g_expw1_h + (size_t)e * DD * HID + col0, HID, DD, smem, acc);
    EPI2_SETUP();
    __half* dst = g_ehidh + ((size_t)e * BB + b) * SS * HID;
#pragma unroll
    for (int mt = 0; mt < 4; mt++)
#pragma unroll
        for (int nt = 0; nt < 8; nt++) {
            int n = col0 + wn * 64 + nt * 8 + 2 * tig;
            float b0 = b1[e * HID + n], bx = b1[e * HID + n + 1];
#pragma unroll
            for (int hf = 0; hf < 2; hf++) {
                int m = row0 + wm * 64 + mt * 16 + g + hf * 8;
                *(__half2*)&dst[(size_t)m * HID + n] =
                    __floats2half2_rn(wv * geluf(acc[mt][nt][2 * hf] + b0),
                                      wv * geluf(acc[mt][nt][2 * hf + 1] + bx));
            }
        }
}

// expert out slot-parallel: g_part[slot] = ehid[e,b] @ w2[e] + wv*b2[e]
__global__ void __launch_bounds__(128) expert_out_g2(const float* __restrict__ b2)
{
    extern __shared__ __half smem[];
    int b = blockIdx.z >> 2, slot = blockIdx.z & 3;
    int e = 0; float wv = 0.0f;
    {
        int cnt = -1;
        for (int j = 0; j < EE; j++) {
            float t = g_wgt[b * EE + j];
            if (t != 0.0f) { cnt++; if (cnt == slot) { e = j; wv = t; break; } }
        }
    }
    int row0 = blockIdx.y * 128, col0 = blockIdx.x * 128;
    float acc[4][8][4] = {};
    gemm2(g_ehidh + (((size_t)e * BB + b) * SS + row0) * HID, HID,
          g_expw2_h + (size_t)e * HID * DD + col0, DD, HID, smem, acc);
    EPI2_SETUP();
    float* dst = g_part[slot];
#pragma unroll
    for (int mt = 0; mt < 4; mt++)
#pragma unroll
        for (int nt = 0; nt < 8; nt++) {
            int n = col0 + wn * 64 + nt * 8 + 2 * tig;
            float b0 = wv * b2[e * DD + n], b1v = wv * b2[e * DD + n + 1];
#pragma unroll
            for (int hf = 0; hf < 2; hf++) {
                int m = row0 + wm * 64 + mt * 16 + g + hf * 8;
                *(float2*)&dst[((size_t)b * SS + m) * DD + n] =
                    make_float2(acc[mt][nt][2 * hf] + b0,
                                acc[mt][nt][2 * hf + 1] + b1v);
            }
        }
}

// shared hidden: shid = gelu(h2h @ sh_w1 + sh_b1) (fp16 out)
__global__ void __launch_bounds__(128) shared_hid_g2(const float* __restrict__ b1)
{
    extern __shared__ __half smem[];
    int row0 = blockIdx.y * 128, col0 = blockIdx.x * 128;
    float acc[4][8][4] = {};
    gemm2(g_h2h + (size_t)row0 * DD, DD, g_shw1_h + col0, SHH, DD, smem, acc);
    EPI2_SETUP();
#pragma unroll
    for (int mt = 0; mt < 4; mt++)
#pragma unroll
        for (int nt = 0; nt < 8; nt++) {
            int n = col0 + wn * 64 + nt * 8 + 2 * tig;
            float b0 = b1[n], bx = b1[n + 1];
#pragma unroll
            for (int hf = 0; hf < 2; hf++) {
                int m = row0 + wm * 64 + mt * 16 + g + hf * 8;
                *(__half2*)&g_shidh[(size_t)m * SHH + n] =
                    __floats2half2_rn(geluf(acc[mt][nt][2 * hf] + b0),
                                      geluf(acc[mt][nt][2 * hf + 1] + bx));
            }
        }
}

// final split-K chunk c: g_part[4+c] = shid[:, c*768:+768] @ sh_w2[c*768:+768, :]
__global__ void __launch_bounds__(128) final_split_g2()
{
    extern __shared__ __half smem[];
    int c = blockIdx.z;
    int row0 = blockIdx.y * 128, col0 = blockIdx.x * 128;
    float acc[4][8][4] = {};
    gemm2(g_shidh + (size_t)row0 * SHH + c * 768, SHH,
          g_shw2_h + (size_t)(c * 768) * DD + col0, DD, 768, smem, acc);
    EPI2_SETUP();
    float* dst = g_part[4 + c];
#pragma unroll
    for (int mt = 0; mt < 4; mt++)
#pragma unroll
        for (int nt = 0; nt < 8; nt++) {
            int n = col0 + wn * 64 + nt * 8 + 2 * tig;
#pragma unroll
            for (int hf = 0; hf < 2; hf++) {
                int m = row0 + wm * 64 + mt * 16 + g + hf * 8;
                *(float2*)&dst[(size_t)m * DD + n] =
                    make_float2(acc[mt][nt][2 * hf], acc[mt][nt][2 * hf + 1]);
            }
        }
}

// ---------------- flash attention (fp16, P in registers) ----------------
#define FLDA 72
#define FLASH_SMEM (3 * 128 * FLDA * 2)

__global__ void __launch_bounds__(256, 1) flash_tc()
{
    extern __shared__ __half hsm[];
    __half* sQ = hsm;
    __half* sK = hsm + 128 * FLDA;
    __half* sV = hsm + 2 * 128 * FLDA;

    const int bh = blockIdx.y;
    const int q0 = blockIdx.x * 128;
    const __half* Qg = g_qh + ((size_t)bh * SS + q0) * DH;
    const __half* Kg = g_kh + (size_t)bh * SS * DH;
    const __half* Vg = g_vh + (size_t)bh * SS * DH;

    const int tid = threadIdx.x, lane = tid & 31, w = tid >> 5;
    const int l16 = lane & 15, lh = lane >> 4;
    const int g = lane >> 2, tig = lane & 3;

#define FCOPY(dst, src)                                                       \
    { _Pragma("unroll")                                                       \
      for (int i = 0; i < 4; i++) {                                           \
          int e = tid + i * 256; int r = e >> 3, v = e & 7;                   \
          cp16h((dst) + r * FLDA + v * 8, (src) + (size_t)r * 64 + v * 8); } }

    FCOPY(sQ, Qg);
    FCOPY(sK, Kg);
    asm volatile("cp.async.commit_group;");
    FCOPY(sV, Vg);
    asm volatile("cp.async.commit_group;");

    float acc_o[8][4] = {};
    float mrun[2] = {-1e30f, -1e30f};
    float lrun[2] = {0.0f, 0.0f};

    const uint32_t sQa = (uint32_t)__cvta_generic_to_shared(sQ);
    const uint32_t sKa = (uint32_t)__cvta_generic_to_shared(sK);
    const uint32_t sVa = (uint32_t)__cvta_generic_to_shared(sV);

    for (int st = 0; st < 4; st++) {
        asm volatile("cp.async.wait_group 1;" ::: "memory");
        __syncthreads();

        float s[16][4] = {};
#pragma unroll
        for (int kk = 0; kk < 4; kk++) {
            int k0 = kk * 16;
            uint32_t a[4];
            ldsm4(a[0], a[1], a[2], a[3],
                  sQa + 2u * ((w * 16 + l16) * FLDA + k0 + lh * 8));
#pragma unroll
            for (int p = 0; p < 8; p++) {
                uint32_t r0, r1, r2, r3;
                ldsm4(r0, r1, r2, r3,
                      sKa + 2u * ((p * 16 + l16) * FLDA + k0 + lh * 8));
                uint32_t b0[2] = {r0, r2}, b1[2] = {r1, r3};
                mma_f16(s[2 * p], a, b0);
                mma_f16(s[2 * p + 1], a, b1);
            }
        }

        float tmax[2] = {-1e30f, -1e30f};
#pragma unroll
        for (int nt = 0; nt < 16; nt++) {
            tmax[0] = fmaxf(tmax[0], fmaxf(s[nt][0], s[nt][1]));
            tmax[1] = fmaxf(tmax[1], fmaxf(s[nt][2], s[nt][3]));
        }
#pragma unroll
        for (int o = 1; o < 4; o <<= 1) {
            tmax[0] = fmaxf(tmax[0], __shfl_xor_sync(0xffffffffu, tmax[0], o));
            tmax[1] = fmaxf(tmax[1], __shfl_xor_sync(0xffffffffu, tmax[1], o));
        }
        float mnew[2], corr[2], rsum[2] = {0.0f, 0.0f};
#pragma unroll
        for (int h = 0; h < 2; h++) {
            mnew[h] = fmaxf(mrun[h], tmax[h] * 0.125f);
            corr[h] = __expf(mrun[h] - mnew[h]);
            mrun[h] = mnew[h];
        }
        uint32_t ph[16][2];
#pragma unroll
        for (int nt = 0; nt < 16; nt++) {
            float p0 = __expf(s[nt][0] * 0.125f - mnew[0]);
            float p1 = __expf(s[nt][1] * 0.125f - mnew[0]);
            float p2 = __expf(s[nt][2] * 0.125f - mnew[1]);
            float p3 = __expf(s[nt][3] * 0.125f - mnew[1]);
            rsum[0] += p0 + p1; rsum[1] += p2 + p3;
            ph[nt][0] = packh2(p0, p1);
            ph[nt][1] = packh2(p2, p3);
        }
#pragma unroll
        for (int o = 1; o < 4; o <<= 1) {
            rsum[0] += __shfl_xor_sync(0xffffffffu, rsum[0], o);
            rsum[1] += __shfl_xor_sync(0xffffffffu, rsum[1], o);
        }
        lrun[0] = lrun[0] * corr[0] + rsum[0];
        lrun[1] = lrun[1] * corr[1] + rsum[1];
#pragma unroll
        for (int nt = 0; nt < 8; nt++) {
            acc_o[nt][0] *= corr[0]; acc_o[nt][1] *= corr[0];
            acc_o[nt][2] *= corr[1]; acc_o[nt][3] *= corr[1];
        }

        asm volatile("cp.async.wait_group 0;" ::: "memory");
        __syncthreads();
        if (st < 3) {
            FCOPY(sK, Kg + (size_t)(st + 1) * 128 * 64);
            asm volatile("cp.async.commit_group;");
        }

#pragma unroll
        for (int j = 0; j < 8; j++) {
            int k0 = j * 16;
            uint32_t a[4] = {ph[2 * j][0], ph[2 * j][1], ph[2 * j + 1][0], ph[2 * j + 1][1]};
#pragma unroll
            for (int p = 0; p < 4; p++) {
                uint32_t r0, r1, r2, r3;
                ldsm4t(r0, r1, r2, r3,
                       sVa + 2u * ((k0 + l16) * FLDA + p * 16 + lh * 8));
                uint32_t b0[2] = {r0, r1}, b1[2] = {r2, r3};
                mma_f16(acc_o[2 * p], a, b0);
                mma_f16(acc_o[2 * p + 1], a, b1);
            }
        }
        __syncthreads();
        if (st < 3) {
            FCOPY(sV, Vg + (size_t)(st + 1) * 128 * 64);
            asm volatile("cp.async.commit_group;");
        }
    }

    const int b = bh / HH, hh = bh - b * HH;
    const float inv0 = 1.0f / lrun[0], inv1 = 1.0f / lrun[1];
    const int m0 = q0 + w * 16 + g;
#pragma unroll
    for (int nt = 0; nt < 8; nt++) {
        int d = nt * 8 + 2 * tig;
        *(__half2*)&g_aoh[((size_t)b * SS + m0) * DD + hh * DH + d] =
            __floats2half2_rn(acc_o[nt][0] * inv0, acc_o[nt][1] * inv0);
        *(__half2*)&g_aoh[((size_t)b * SS + m0 + 8) * DD + hh * DH + d] =
            __floats2half2_rn(acc_o[nt][2] * inv1, acc_o[nt][3] * inv1);
    }
#undef FCOPY
}

// ---------------- conversion kernels ----------------
__global__ void f2h_kernel(const float* __restrict__ in, __half* __restrict__ out, int n8)
{
    int i = blockIdx.x * 256 + threadIdx.x;
    if (i >= n8) return;
    float4 a = ((const float4*)in)[2 * i];
    float4 b = ((const float4*)in)[2 * i + 1];
    uint4 u;
    u.x = packh2(a.x, a.y); u.y = packh2(a.z, a.w);
    u.z = packh2(b.x, b.y); u.w = packh2(b.z, b.w);
    ((uint4*)out)[i] = u;
}

// convert active experts' w1+w2 (gated by g_eact)
__global__ void expconv_kernel(const float* __restrict__ w1, const float* __restrict__ w2)
{
    int e = blockIdx.y;
    if (!g_eact[e]) return;
    int i = blockIdx.x * 256 + threadIdx.x;
    const int n8 = DD * HID / 8;
    const float* src; __half* dst; int j;
    if (i < n8) { src = w1 + (size_t)e * DD * HID; dst = g_expw1_h + (size_t)e * DD * HID; j = i; }
    else        { src = w2 + (size_t)e * HID * DD; dst = g_expw2_h + (size_t)e * HID * DD; j = i - n8; }
    float4 a = ((const float4*)src)[2 * j];
    float4 b = ((const float4*)src)[2 * j + 1];
    uint4 u;
    u.x = packh2(a.x, a.y); u.y = packh2(a.z, a.w);
    u.z = packh2(b.x, b.y); u.w = packh2(b.z, b.w);
    ((uint4*)dst)[j] = u;
}

__global__ void eact_init_kernel()
{
    if (threadIdx.x < EE) g_eact[threadIdx.x] = 0;
}

// ---------------- elementwise kernels ----------------
__global__ void ln_kernel(const float* __restrict__ in, const float* __restrict__ g,
                          const float* __restrict__ b, __half* __restrict__ outh,
                          float* __restrict__ outf)
{
    __shared__ float red[256];
    size_t row = blockIdx.x;
    const float* xr = in + row * DD;
    int tid = threadIdx.x;
    float x0 = xr[tid], x1 = xr[tid + 256], x2 = xr[tid + 512];
    float total = blockReduceSum(x0 + x1 + x2, red);
    float mean = total * (1.0f / DD);
    float d0 = x0 - mean, d1 = x1 - mean, d2 = x2 - mean;
    float var = blockReduceSum(d0 * d0 + d1 * d1 + d2 * d2, red) * (1.0f / DD);
    float rstd = rsqrtf(var + 1e-5f);
    float r0 = d0 * rstd * g[tid]       + b[tid];
    float r1 = d1 * rstd * g[tid + 256] + b[tid + 256];
    float r2 = d2 * rstd * g[tid + 512] + b[tid + 512];
    outh[row * DD + tid]       = __float2half_rn(r0);
    outh[row * DD + tid + 256] = __float2half_rn(r1);
    outh[row * DD + tid + 512] = __float2half_rn(r2);
    if (outf) {
        outf[row * DD + tid]       = r0;
        outf[row * DD + tid + 256] = r1;
        outf[row * DD + tid + 512] = r2;
    }
}

__global__ void seqmean_kernel()
{
    int b = blockIdx.y;
    int d = blockIdx.x * 256 + threadIdx.x;
    const float* p = g_h2f + (size_t)b * SS * DD + d;
    float s = 0.0f;
    for (int i = 0; i < SS; i++) s += p[(size_t)i * DD];
    g_seq[b * DD + d] = s * (1.0f / SS);
}

__global__ void router_kernel(const float* __restrict__ w1, const float* __restrict__ b1,
                              const float* __restrict__ w2, const float* __restrict__ b2)
{
    __shared__ float s_in[DD];
    __shared__ float s_hid[DD];
    __shared__ float s_logits[EE];
    int b = blockIdx.x;
    int tid = threadIdx.x;
    for (int i = tid; i < DD; i += 256) s_in[i] = g_seq[b * DD + i];
    __syncthreads();
    for (int j = tid; j < DD; j += 256) {
        float a = b1[j];
        for (int d = 0; d < DD; d++) a = fmaf(s_in[d], w1[(size_t)d * DD + j], a);
        s_hid[j] = geluf(a);
    }
    __syncthreads();
    if (tid < EE) {
        float a = b2[tid];
        for (int d = 0; d < DD; d++) a = fmaf(s_hid[d], w2[(size_t)d * EE + tid], a);
        s_logits[tid] = a;
    }
    __syncthreads();
    if (tid == 0) {
        float p[EE];
        float mx = -1e30f;
        for (int e = 0; e < EE; e++) mx = fmaxf(mx, s_logits[e]);
        float sum = 0.0f;
        for (int e = 0; e < EE; e++) { p[e] = expf(s_logits[e] - mx); sum += p[e]; }
        float inv = 1.0f / sum;
        for (int e = 0; e < EE; e++) p[e] *= inv;
        int   idx[KK];
        float val[KK];
        bool used[EE] = {};
        for (int k = 0; k < KK; k++) {
            int best = -1; float bv = -1e30f;
            for (int e = 0; e < EE; e++)
                if (!used[e] && p[e] > bv) { bv = p[e]; best = e; }
            used[best] = true; idx[k] = best; val[k] = bv;
        }
        float m2 = val[0];
        float s2 = 0.0f, tw[KK];
        for (int k = 0; k < KK; k++) { tw[k] = expf(val[k] - m2); s2 += tw[k]; }
        float inv2 = 1.0f / s2;
        for (int e = 0; e < EE; e++) g_wgt[b * EE + e] = 0.0f;
        for (int k = 0; k < KK; k++) {
            g_wgt[b * EE + idx[k]] = tw[k] * inv2;
            g_eact[idx[k]] = 1;
        }
    }
}

// out = x2 + sum(partials) + sh_b2
__global__ void final_sum_kernel(const float* __restrict__ b2, float* __restrict__ out)
{
    int i = blockIdx.x * 256 + threadIdx.x;
    int n = (i % (DD / 4)) * 4;
    float4 r = *(const float4*)(g_x2 + (size_t)i * 4);
#pragma unroll
    for (int j = 0; j < 8; j++) {
        float4 p = *(const float4*)(g_part[j] + (size_t)i * 4);
        r.x += p.x; r.y += p.y; r.z += p.z; r.w += p.w;
    }
    float4 bb = *(const float4*)(b2 + n);
    r.x += bb.x; r.y += bb.y; r.z += bb.z; r.w += bb.w;
    *(float4*)(out + (size_t)i * 4) = r;
}

// ---------------- launch ----------------
extern "C" void kernel_launch(void* const* d_in, const int* in_sizes, int n_in,
                              void* d_out, int out_size)
{
    const float* x         = (const float*)d_in[0];
    const float* ln1_g     = (const float*)d_in[1];
    const float* ln1_b     = (const float*)d_in[2];
    const float* qkv_w     = (const float*)d_in[3];
    const float* proj_w    = (const float*)d_in[4];
    const float* proj_b    = (const float*)d_in[5];
    const float* ln2_g     = (const float*)d_in[6];
    const float* ln2_b     = (const float*)d_in[7];
    const float* router_w1 = (const float*)d_in[8];
    const float* router_b1 = (const float*)d_in[9];
    const float* router_w2 = (const float*)d_in[10];
    const float* router_b2 = (const float*)d_in[11];
    const float* exp_w1    = (const float*)d_in[12];
    const float* exp_b1    = (const float*)d_in[13];
    const float* exp_w2    = (const float*)d_in[14];
    const float* exp_b2    = (const float*)d_in[15];
    const float* sh_w1     = (const float*)d_in[16];
    const float* sh_b1     = (const float*)d_in[17];
    const float* sh_w2     = (const float*)d_in[18];
    const float* sh_b2     = (const float*)d_in[19];
    float* out = (float*)d_out;

    cudaFuncSetAttribute(qkv_g2,        cudaFuncAttributeMaxDynamicSharedMemorySize, SMEMB_G2);
    cudaFuncSetAttribute(proj_g2,       cudaFuncAttributeMaxDynamicSharedMemorySize, SMEMB_G2);
    cudaFuncSetAttribute(expert_hid_g2, cudaFuncAttributeMaxDynamicSharedMemorySize, SMEMB_G2);
    cudaFuncSetAttribute(expert_out_g2, cudaFuncAttributeMaxDynamicSharedMemorySize, SMEMB_G2);
    cudaFuncSetAttribute(shared_hid_g2, cudaFuncAttributeMaxDynamicSharedMemorySize, SMEMB_G2);
    cudaFuncSetAttribute(final_split_g2,cudaFuncAttributeMaxDynamicSharedMemorySize, SMEMB_G2);
    cudaFuncSetAttribute(flash_tc,      cudaFuncAttributeMaxDynamicSharedMemorySize, FLASH_SMEM);

    __half* wq;  cudaGetSymbolAddress((void**)&wq,  g_qkvw_h);
    __half* wp;  cudaGetSymbolAddress((void**)&wp,  g_projw_h);
    __half* w1;  cudaGetSymbolAddress((void**)&w1,  g_shw1_h);
    __half* w2;  cudaGetSymbolAddress((void**)&w2,  g_shw2_h);
    __half* h1h; cudaGetSymbolAddress((void**)&h1h, g_h1h);
    __half* h2h; cudaGetSymbolAddress((void**)&h2h, g_h2h);
    float*  h2f; cudaGetSymbolAddress((void**)&h2f, g_h2f);
    float*  x2;  cudaGetSymbolAddress((void**)&x2,  g_x2);

    // weight conversions ([K][N] fp16 mirrors)
    f2h_kernel<<<(DD*3*DD/8 + 255)/256, 256>>>(qkv_w, wq, DD*3*DD/8);
    f2h_kernel<<<(DD*DD/8   + 255)/256, 256>>>(proj_w, wp, DD*DD/8);
    f2h_kernel<<<(DD*SHH/8  + 255)/256, 256>>>(sh_w1, w1, DD*SHH/8);
    f2h_kernel<<<(SHH*DD/8  + 255)/256, 256>>>(sh_w2, w2, SHH*DD/8);

    // attention branch
    ln_kernel<<<NTOK, 256>>>(x, ln1_g, ln1_b, h1h, nullptr);
    qkv_g2<<<dim3(18, 32), 128, SMEMB_G2>>>();
    flash_tc<<<dim3(4, BHN), 256, FLASH_SMEM>>>();
    proj_g2<<<dim3(6, 32), 128, SMEMB_G2>>>(proj_b, x);

    // MoE branch
    ln_kernel<<<NTOK, 256>>>(x2, ln2_g, ln2_b, h2h, h2f);
    seqmean_kernel<<<dim3(3, BB), 256>>>();
    eact_init_kernel<<<1, 32>>>();
    router_kernel<<<BB, 256>>>(router_w1, router_b1, router_w2, router_b2);
    expconv_kernel<<<dim3(2*DD*HID/8/256, EE), 256>>>(exp_w1, exp_w2);
    expert_hid_g2<<<dim3(12, 4, EE * BB), 128, SMEMB_G2>>>(exp_b1);
    expert_out_g2<<<dim3(6, 4, BB * KK), 128, SMEMB_G2>>>(exp_b2);
    shared_hid_g2<<<dim3(24, 32), 128, SMEMB_G2>>>(sh_b1);
    final_split_g2<<<dim3(6, 32, 4), 128, SMEMB_G2>>>();
    final_sum_kernel<<<NTOK * DD / 4 / 256, 256>>>(sh_b2, out);
}